// round 1
// baseline (speedup 1.0000x reference)
#include <cuda_runtime.h>
#include <math.h>

#define BS   4
#define SEQ  2048
#define DM   1024
#define NH   16
#define DK   64
#define MTOT (BS * SEQ)   // 8192

// Scratch (device globals — no allocation allowed)
__device__ float g_qp[MTOT * DM];
__device__ float g_kp[MTOT * DM];
__device__ float g_vp[MTOT * DM];
__device__ float g_ctx[MTOT * DM];

// ---------------------------------------------------------------------------
// GEMM: C[M, N] = A[M, K] @ W[K, N] + bias[N], K = N = 1024, M = 8192
// Block tile 128x128, K-tile 16, 256 threads, 8x8 per-thread microtile.
// ---------------------------------------------------------------------------
#define GBM 128
#define GBN 128
#define GBK 16
#define GPAD 4

__global__ __launch_bounds__(256) void gemm_bias_kernel(
    const float* __restrict__ A, const float* __restrict__ W,
    const float* __restrict__ bias, float* __restrict__ C)
{
    __shared__ float AsT[GBK][GBM + GPAD];   // [k][m]
    __shared__ float Bs [GBK][GBN + GPAD];   // [k][n]

    const int tid = threadIdx.x;
    const int tx = tid & 15;        // 0..15 (n dir)
    const int ty = tid >> 4;        // 0..15 (m dir)
    const int bm = blockIdx.y * GBM;
    const int bn = blockIdx.x * GBN;

    float acc[8][8];
#pragma unroll
    for (int i = 0; i < 8; i++)
#pragma unroll
        for (int j = 0; j < 8; j++) acc[i][j] = 0.f;

    for (int k0 = 0; k0 < DM; k0 += GBK) {
        // --- load A tile (128 rows x 16 k), transposed into AsT ---
        {
            const int r  = tid >> 1;          // 0..127
            const int kk = (tid & 1) * 8;     // 0 or 8
            const float4* src =
                (const float4*)&A[(size_t)(bm + r) * DM + k0 + kk];
            float4 v0 = src[0], v1 = src[1];
            AsT[kk + 0][r] = v0.x; AsT[kk + 1][r] = v0.y;
            AsT[kk + 2][r] = v0.z; AsT[kk + 3][r] = v0.w;
            AsT[kk + 4][r] = v1.x; AsT[kk + 5][r] = v1.y;
            AsT[kk + 6][r] = v1.z; AsT[kk + 7][r] = v1.w;
        }
        // --- load W tile (16 k x 128 n) ---
        {
            const int kr = tid >> 4;          // 0..15
            const int n  = (tid & 15) * 8;    // 0..120
            const float4* src =
                (const float4*)&W[(size_t)(k0 + kr) * DM + bn + n];
            *(float4*)&Bs[kr][n]     = src[0];
            *(float4*)&Bs[kr][n + 4] = src[1];
        }
        __syncthreads();

#pragma unroll
        for (int k = 0; k < GBK; k++) {
            float a[8], b[8];
            *(float4*)&a[0] = *(float4*)&AsT[k][ty * 8];
            *(float4*)&a[4] = *(float4*)&AsT[k][ty * 8 + 4];
            *(float4*)&b[0] = *(float4*)&Bs[k][tx * 8];
            *(float4*)&b[4] = *(float4*)&Bs[k][tx * 8 + 4];
#pragma unroll
            for (int i = 0; i < 8; i++)
#pragma unroll
                for (int j = 0; j < 8; j++)
                    acc[i][j] = fmaf(a[i], b[j], acc[i][j]);
        }
        __syncthreads();
    }

    // --- epilogue: + bias, store ---
#pragma unroll
    for (int i = 0; i < 8; i++) {
        const int row = bm + ty * 8 + i;
#pragma unroll
        for (int j = 0; j < 8; j += 4) {
            const int col = bn + tx * 8 + j;
            float4 o;
            o.x = acc[i][j + 0] + bias[col + 0];
            o.y = acc[i][j + 1] + bias[col + 1];
            o.z = acc[i][j + 2] + bias[col + 2];
            o.w = acc[i][j + 3] + bias[col + 3];
            *(float4*)&C[(size_t)row * DM + col] = o;
        }
    }
}

// ---------------------------------------------------------------------------
// Flash attention (fp32). One CTA per (b, h, 64-row q-tile); 64-row KV tiles.
// Layout of projected tensors: [B*S, H*DK] row-major; head h = cols h*64..+64.
// ---------------------------------------------------------------------------
#define APAD 4
#define AST  (DK + APAD)   // 68
#define ATILE 64

__global__ __launch_bounds__(256) void attn_kernel(
    const float* __restrict__ Q, const float* __restrict__ K,
    const float* __restrict__ V, float* __restrict__ O)
{
    extern __shared__ float sm[];
    float (*Qs) [AST] = (float(*)[AST])(sm);
    float (*KsT)[AST] = (float(*)[AST])(sm + 1 * ATILE * AST); // [k][c]
    float (*Vs) [AST] = (float(*)[AST])(sm + 2 * ATILE * AST); // [c][d]
    float (*Ps) [AST] = (float(*)[AST])(sm + 3 * ATILE * AST); // [r][c]

    const int tid = threadIdx.x;
    const int r  = tid >> 2;       // query row within tile, 0..63
    const int g  = tid & 3;        // column group, 0..3
    const int cb = g * 16;

    const int b  = blockIdx.z;
    const int h  = blockIdx.y;
    const int qt = blockIdx.x;

    const float* Qb = Q + (size_t)(b * SEQ + qt * ATILE) * DM + h * DK;
    const float* Kb = K + (size_t)b * SEQ * DM + h * DK;
    const float* Vb = V + (size_t)b * SEQ * DM + h * DK;

    // load Q tile
#pragma unroll
    for (int j = 0; j < 16; j += 4)
        *(float4*)&Qs[r][cb + j] =
            *(const float4*)&Qb[(size_t)r * DM + cb + j];

    float m_i = -INFINITY, l_i = 0.f;
    float o_acc[16];
#pragma unroll
    for (int j = 0; j < 16; j++) o_acc[j] = 0.f;

    for (int t = 0; t < SEQ / ATILE; t++) {
        __syncthreads();   // prev-iter PV reads done before overwrite
        // load K (transposed) and V tiles
#pragma unroll
        for (int j = 0; j < 16; j += 4) {
            float4 kv = *(const float4*)
                &Kb[(size_t)(t * ATILE + r) * DM + cb + j];
            KsT[cb + j + 0][r] = kv.x;
            KsT[cb + j + 1][r] = kv.y;
            KsT[cb + j + 2][r] = kv.z;
            KsT[cb + j + 3][r] = kv.w;
            *(float4*)&Vs[r][cb + j] = *(const float4*)
                &Vb[(size_t)(t * ATILE + r) * DM + cb + j];
        }
        __syncthreads();

        // scores: s[j] = q_row . k_col(cb+j), scaled
        float s[16];
#pragma unroll
        for (int j = 0; j < 16; j++) s[j] = 0.f;
#pragma unroll 8
        for (int k = 0; k < DK; k++) {
            const float qv = Qs[r][k];
#pragma unroll
            for (int j = 0; j < 16; j++)
                s[j] = fmaf(qv, KsT[k][cb + j], s[j]);
        }

        float mt = -INFINITY;
#pragma unroll
        for (int j = 0; j < 16; j++) {
            s[j] *= 0.125f;   // 1/sqrt(64)
            mt = fmaxf(mt, s[j]);
        }
        mt = fmaxf(mt, __shfl_xor_sync(0xffffffffu, mt, 1));
        mt = fmaxf(mt, __shfl_xor_sync(0xffffffffu, mt, 2));

        const float m_new = fmaxf(m_i, mt);
        const float corr  = __expf(m_i - m_new);
        float ps = 0.f;
#pragma unroll
        for (int j = 0; j < 16; j++) {
            s[j] = __expf(s[j] - m_new);
            ps += s[j];
        }
        ps += __shfl_xor_sync(0xffffffffu, ps, 1);
        ps += __shfl_xor_sync(0xffffffffu, ps, 2);
        l_i = l_i * corr + ps;
#pragma unroll
        for (int j = 0; j < 16; j++) o_acc[j] *= corr;
#pragma unroll
        for (int j = 0; j < 16; j += 4)
            *(float4*)&Ps[r][cb + j] = make_float4(s[j], s[j+1], s[j+2], s[j+3]);
        m_i = m_new;
        __syncthreads();

        // PV: o_acc[d] += sum_c P[r][c] * V[c][cb+d]
#pragma unroll 8
        for (int c = 0; c < ATILE; c++) {
            const float p = Ps[r][c];
#pragma unroll
            for (int j = 0; j < 16; j++)
                o_acc[j] = fmaf(p, Vs[c][cb + j], o_acc[j]);
        }
    }

    const float inv = 1.f / l_i;
    float* Ob = O + (size_t)(b * SEQ + qt * ATILE + r) * DM + h * DK + cb;
#pragma unroll
    for (int j = 0; j < 16; j += 4) {
        float4 o;
        o.x = o_acc[j + 0] * inv; o.y = o_acc[j + 1] * inv;
        o.z = o_acc[j + 2] * inv; o.w = o_acc[j + 3] * inv;
        *(float4*)&Ob[j] = o;
    }
}

// ---------------------------------------------------------------------------
extern "C" void kernel_launch(void* const* d_in, const int* in_sizes, int n_in,
                              void* d_out, int out_size)
{
    const float* q  = (const float*)d_in[0];
    const float* k  = (const float*)d_in[1];
    const float* v  = (const float*)d_in[2];
    const float* wq = (const float*)d_in[3];
    const float* bq = (const float*)d_in[4];
    const float* wk = (const float*)d_in[5];
    const float* bk = (const float*)d_in[6];
    const float* wv = (const float*)d_in[7];
    const float* bv = (const float*)d_in[8];
    const float* wo = (const float*)d_in[9];
    const float* bo = (const float*)d_in[10];
    float* out = (float*)d_out;

    float *qp, *kp, *vp, *ctx;
    cudaGetSymbolAddress((void**)&qp,  g_qp);
    cudaGetSymbolAddress((void**)&kp,  g_kp);
    cudaGetSymbolAddress((void**)&vp,  g_vp);
    cudaGetSymbolAddress((void**)&ctx, g_ctx);

    const dim3 ggrid(DM / GBN, MTOT / GBM);   // (8, 64)
    gemm_bias_kernel<<<ggrid, 256>>>(q, wq, bq, qp);
    gemm_bias_kernel<<<ggrid, 256>>>(k, wk, bk, kp);
    gemm_bias_kernel<<<ggrid, 256>>>(v, wv, bv, vp);

    const int smem_attn = 4 * ATILE * AST * sizeof(float);  // 69632 B
    cudaFuncSetAttribute(attn_kernel,
                         cudaFuncAttributeMaxDynamicSharedMemorySize,
                         smem_attn);
    const dim3 agrid(SEQ / ATILE, NH, BS);    // (32, 16, 4)
    attn_kernel<<<agrid, 256, smem_attn>>>(qp, kp, vp, ctx);

    gemm_bias_kernel<<<ggrid, 256>>>(ctx, wo, bo, out);
}

// round 3
// speedup vs baseline: 2.8147x; 2.8147x over previous
#include <cuda_runtime.h>
#include <math.h>

#define BS   4
#define SEQ  2048
#define DM   1024
#define NH   16
#define DK   64
#define MTOT (BS * SEQ)   // 8192

// Scratch (device globals — no allocation allowed)
__device__ float g_qp[MTOT * DM];
__device__ float g_kp[MTOT * DM];
__device__ float g_vp[MTOT * DM];
__device__ float g_ctx[MTOT * DM];

// ---------------------------------------------------------------------------
// GEMM: C[M, N] = A[M, K] @ W[K, N] + bias[N], K = N = 1024, M = 8192
// Block tile 128x128, K-tile 16, 256 threads, 8x8 per-thread microtile.
// ---------------------------------------------------------------------------
#define GBM 128
#define GBN 128
#define GBK 16
#define GPAD 4

__global__ __launch_bounds__(256) void gemm_bias_kernel(
    const float* __restrict__ A, const float* __restrict__ W,
    const float* __restrict__ bias, float* __restrict__ C)
{
    __shared__ float AsT[GBK][GBM + GPAD];   // [k][m]
    __shared__ float Bs [GBK][GBN + GPAD];   // [k][n]

    const int tid = threadIdx.x;
    const int tx = tid & 15;        // 0..15 (n dir)
    const int ty = tid >> 4;        // 0..15 (m dir)
    const int bm = blockIdx.y * GBM;
    const int bn = blockIdx.x * GBN;

    float acc[8][8];
#pragma unroll
    for (int i = 0; i < 8; i++)
#pragma unroll
        for (int j = 0; j < 8; j++) acc[i][j] = 0.f;

    for (int k0 = 0; k0 < DM; k0 += GBK) {
        {
            const int r  = tid >> 1;          // 0..127
            const int kk = (tid & 1) * 8;     // 0 or 8
            const float4* src =
                (const float4*)&A[(size_t)(bm + r) * DM + k0 + kk];
            float4 v0 = src[0], v1 = src[1];
            AsT[kk + 0][r] = v0.x; AsT[kk + 1][r] = v0.y;
            AsT[kk + 2][r] = v0.z; AsT[kk + 3][r] = v0.w;
            AsT[kk + 4][r] = v1.x; AsT[kk + 5][r] = v1.y;
            AsT[kk + 6][r] = v1.z; AsT[kk + 7][r] = v1.w;
        }
        {
            const int kr = tid >> 4;          // 0..15
            const int n  = (tid & 15) * 8;    // 0..120
            const float4* src =
                (const float4*)&W[(size_t)(k0 + kr) * DM + bn + n];
            *(float4*)&Bs[kr][n]     = src[0];
            *(float4*)&Bs[kr][n + 4] = src[1];
        }
        __syncthreads();

#pragma unroll
        for (int k = 0; k < GBK; k++) {
            float a[8], b[8];
            *(float4*)&a[0] = *(float4*)&AsT[k][ty * 8];
            *(float4*)&a[4] = *(float4*)&AsT[k][ty * 8 + 4];
            *(float4*)&b[0] = *(float4*)&Bs[k][tx * 8];
            *(float4*)&b[4] = *(float4*)&Bs[k][tx * 8 + 4];
#pragma unroll
            for (int i = 0; i < 8; i++)
#pragma unroll
                for (int j = 0; j < 8; j++)
                    acc[i][j] = fmaf(a[i], b[j], acc[i][j]);
        }
        __syncthreads();
    }

#pragma unroll
    for (int i = 0; i < 8; i++) {
        const int row = bm + ty * 8 + i;
#pragma unroll
        for (int j = 0; j < 8; j += 4) {
            const int col = bn + tx * 8 + j;
            float4 o;
            o.x = acc[i][j + 0] + bias[col + 0];
            o.y = acc[i][j + 1] + bias[col + 1];
            o.z = acc[i][j + 2] + bias[col + 2];
            o.w = acc[i][j + 3] + bias[col + 3];
            *(float4*)&C[(size_t)row * DM + col] = o;
        }
    }
}

// ---------------------------------------------------------------------------
// Flash attention v2 (fp32, register-blocked).
// CTA: one (b, h, 128-row q-tile). KV tiles of 64.
// 256 threads as 16x16 grid: ty -> 8 q-rows, tx -> 4 kv-cols (QK) / 4 d-cols (PV).
// Both QK^T and PV are 8x4-microtile GEMMs fed from transposed smem tiles.
// ---------------------------------------------------------------------------
#define QT   128            // q rows per CTA
#define CT   64             // kv rows per tile
#define QPAD 4
#define QST  (QT + QPAD)    // 132
#define KST  (CT + QPAD)    // 68
#define VST  (DK + 8)       // 72 (float4-aligned rows)

__global__ __launch_bounds__(256) void attn_kernel(
    const float* __restrict__ Q, const float* __restrict__ K,
    const float* __restrict__ V, float* __restrict__ O)
{
    extern __shared__ float sm[];
    float (*QsT)[QST] = (float(*)[QST])(sm);                        // [k][r]
    float (*KsT)[KST] = (float(*)[KST])(sm + DK * QST);             // [k][c]
    float (*Vs) [VST] = (float(*)[VST])(sm + DK * QST + DK * KST);  // [c][d]
    float (*PsT)[QST] = (float(*)[QST])(sm + DK * QST + DK * KST + CT * VST); // [c][r]

    const int tid = threadIdx.x;
    const int tx = tid & 15;           // 0..15
    const int ty = tid >> 4;           // 0..15
    const int R  = ty * 8;             // first q-row of microtile
    const int C4 = tx * 4;             // first col of microtile

    const int b  = blockIdx.z;
    const int h  = blockIdx.y;
    const int qt = blockIdx.x;

    const float* Qb = Q + (size_t)(b * SEQ + qt * QT) * DM + h * DK;
    const float* Kb = K + (size_t)b * SEQ * DM + h * DK;
    const float* Vb = V + (size_t)b * SEQ * DM + h * DK;

    // ---- load Q tile once, transposed, with 1/sqrt(DK) folded in ----
    {
        const int r  = tid >> 1;             // 0..127
        const int kh = (tid & 1) * 32;       // 0 or 32
        const float4* src = (const float4*)&Qb[(size_t)r * DM + kh];
#pragma unroll
        for (int j = 0; j < 8; j++) {
            float4 v = src[j];
            QsT[kh + j * 4 + 0][r] = v.x * 0.125f;
            QsT[kh + j * 4 + 1][r] = v.y * 0.125f;
            QsT[kh + j * 4 + 2][r] = v.z * 0.125f;
            QsT[kh + j * 4 + 3][r] = v.w * 0.125f;
        }
    }

    float m_i[8], l_i[8], o_acc[8][4];
#pragma unroll
    for (int i = 0; i < 8; i++) {
        m_i[i] = -INFINITY; l_i[i] = 0.f;
#pragma unroll
        for (int j = 0; j < 4; j++) o_acc[i][j] = 0.f;
    }

    for (int t = 0; t < SEQ / CT; t++) {
        __syncthreads();   // KsT/Vs/PsT reads from prev iter done

        // ---- load K (transposed) + V tiles ----
        {
            const int r  = tid >> 2;          // 0..63
            const int ko = (tid & 3) * 16;    // 0,16,32,48
            const float4* ks = (const float4*)&Kb[(size_t)(t * CT + r) * DM + ko];
            const float4* vs = (const float4*)&Vb[(size_t)(t * CT + r) * DM + ko];
#pragma unroll
            for (int j = 0; j < 4; j++) {
                float4 kv = ks[j];
                KsT[ko + j * 4 + 0][r] = kv.x;
                KsT[ko + j * 4 + 1][r] = kv.y;
                KsT[ko + j * 4 + 2][r] = kv.z;
                KsT[ko + j * 4 + 3][r] = kv.w;
                *(float4*)&Vs[r][ko + j * 4] = vs[j];
            }
        }
        __syncthreads();

        // ---- scores S[8][4] = Q(8 rows) . K(4 cols) ----
        float s[8][4];
#pragma unroll
        for (int i = 0; i < 8; i++)
#pragma unroll
            for (int j = 0; j < 4; j++) s[i][j] = 0.f;

#pragma unroll 16
        for (int k = 0; k < DK; k++) {
            float a[8], bb[4];
            *(float4*)&a[0] = *(float4*)&QsT[k][R];
            *(float4*)&a[4] = *(float4*)&QsT[k][R + 4];
            *(float4*)&bb[0] = *(float4*)&KsT[k][C4];
#pragma unroll
            for (int i = 0; i < 8; i++)
#pragma unroll
                for (int j = 0; j < 4; j++)
                    s[i][j] = fmaf(a[i], bb[j], s[i][j]);
        }

        // ---- online softmax (row reductions across tx via 16-lane shfl) ----
#pragma unroll
        for (int i = 0; i < 8; i++) {
            float mt = fmaxf(fmaxf(s[i][0], s[i][1]), fmaxf(s[i][2], s[i][3]));
            mt = fmaxf(mt, __shfl_xor_sync(0xffffffffu, mt, 1));
            mt = fmaxf(mt, __shfl_xor_sync(0xffffffffu, mt, 2));
            mt = fmaxf(mt, __shfl_xor_sync(0xffffffffu, mt, 4));
            mt = fmaxf(mt, __shfl_xor_sync(0xffffffffu, mt, 8));
            const float m_new = fmaxf(m_i[i], mt);
            const float corr  = __expf(m_i[i] - m_new);
            float ps = 0.f;
#pragma unroll
            for (int j = 0; j < 4; j++) {
                s[i][j] = __expf(s[i][j] - m_new);
                ps += s[i][j];
            }
            ps += __shfl_xor_sync(0xffffffffu, ps, 1);
            ps += __shfl_xor_sync(0xffffffffu, ps, 2);
            ps += __shfl_xor_sync(0xffffffffu, ps, 4);
            ps += __shfl_xor_sync(0xffffffffu, ps, 8);
            l_i[i] = l_i[i] * corr + ps;
            m_i[i] = m_new;
#pragma unroll
            for (int j = 0; j < 4; j++) o_acc[i][j] *= corr;
        }

        // ---- store P transposed: PsT[c][r] ----
#pragma unroll
        for (int j = 0; j < 4; j++) {
            float4 p0 = make_float4(s[0][j], s[1][j], s[2][j], s[3][j]);
            float4 p1 = make_float4(s[4][j], s[5][j], s[6][j], s[7][j]);
            *(float4*)&PsT[C4 + j][R]     = p0;
            *(float4*)&PsT[C4 + j][R + 4] = p1;
        }
        __syncthreads();

        // ---- PV: o_acc[8][4] += P(8 rows) . V(4 d-cols) ----
#pragma unroll 16
        for (int c = 0; c < CT; c++) {
            float a[8], bb[4];
            *(float4*)&a[0] = *(float4*)&PsT[c][R];
            *(float4*)&a[4] = *(float4*)&PsT[c][R + 4];
            *(float4*)&bb[0] = *(float4*)&Vs[c][C4];
#pragma unroll
            for (int i = 0; i < 8; i++)
#pragma unroll
                for (int j = 0; j < 4; j++)
                    o_acc[i][j] = fmaf(a[i], bb[j], o_acc[i][j]);
        }
    }

    // ---- epilogue ----
#pragma unroll
    for (int i = 0; i < 8; i++) {
        const float inv = 1.f / l_i[i];
        float4 o;
        o.x = o_acc[i][0] * inv; o.y = o_acc[i][1] * inv;
        o.z = o_acc[i][2] * inv; o.w = o_acc[i][3] * inv;
        float* Ob = O + (size_t)(b * SEQ + qt * QT + R + i) * DM + h * DK + C4;
        *(float4*)&Ob[0] = o;
    }
}

// ---------------------------------------------------------------------------
extern "C" void kernel_launch(void* const* d_in, const int* in_sizes, int n_in,
                              void* d_out, int out_size)
{
    const float* q  = (const float*)d_in[0];
    const float* k  = (const float*)d_in[1];
    const float* v  = (const float*)d_in[2];
    const float* wq = (const float*)d_in[3];
    const float* bq = (const float*)d_in[4];
    const float* wk = (const float*)d_in[5];
    const float* bk = (const float*)d_in[6];
    const float* wv = (const float*)d_in[7];
    const float* bv = (const float*)d_in[8];
    const float* wo = (const float*)d_in[9];
    const float* bo = (const float*)d_in[10];
    float* out = (float*)d_out;

    float *qp, *kp, *vp, *ctx;
    cudaGetSymbolAddress((void**)&qp,  g_qp);
    cudaGetSymbolAddress((void**)&kp,  g_kp);
    cudaGetSymbolAddress((void**)&vp,  g_vp);
    cudaGetSymbolAddress((void**)&ctx, g_ctx);

    const dim3 ggrid(DM / GBN, MTOT / GBM);   // (8, 64)
    gemm_bias_kernel<<<ggrid, 256>>>(q, wq, bq, qp);
    gemm_bias_kernel<<<ggrid, 256>>>(k, wk, bk, kp);
    gemm_bias_kernel<<<ggrid, 256>>>(v, wv, bv, vp);

    const int smem_attn =
        (DK * QST + DK * KST + CT * VST + CT * QST) * (int)sizeof(float);
    cudaFuncSetAttribute(attn_kernel,
                         cudaFuncAttributeMaxDynamicSharedMemorySize,
                         smem_attn);
    const dim3 agrid(SEQ / QT, NH, BS);       // (16, 16, 4)
    attn_kernel<<<agrid, 256, smem_attn>>>(qp, kp, vp, ctx);

    gemm_bias_kernel<<<ggrid, 256>>>(ctx, wo, bo, out);
}

// round 10
// speedup vs baseline: 4.3326x; 1.5392x over previous
#include <cuda_runtime.h>
#include <cuda_bf16.h>
#include <math.h>
#include <stdint.h>

#define BS   4
#define SEQ  2048
#define DM   1024
#define NH   16
#define DK   64
#define MTOT (BS * SEQ)   // 8192

// ---------------- scratch (device globals; no allocation allowed) ----------
__device__ float g_qp[MTOT * DM];
__device__ float g_kp[MTOT * DM];
__device__ float g_vp[MTOT * DM];
__device__ float g_ctx[MTOT * DM];
__device__ __nv_bfloat16 g_ahi[MTOT * DM];
__device__ __nv_bfloat16 g_alo[MTOT * DM];
__device__ __nv_bfloat16 g_bhi[DM * DM];
__device__ __nv_bfloat16 g_blo[DM * DM];

// ---------------- helpers ---------------------------------------------------
__device__ __forceinline__ uint32_t smem_u32(const void* p) {
    uint32_t a;
    asm("{ .reg .u64 t; cvta.to.shared.u64 t, %1; cvt.u32.u64 %0, t; }"
        : "=r"(a) : "l"(p));
    return a;
}
__device__ __forceinline__ void cpa16(uint32_t dst, const void* src) {
    asm volatile("cp.async.cg.shared.global [%0], [%1], 16;"
                 :: "r"(dst), "l"(src));
}
#define CP_COMMIT() asm volatile("cp.async.commit_group;" ::: "memory")
#define CP_WAIT(n)  asm volatile("cp.async.wait_group %0;" :: "n"(n) : "memory")

__device__ __forceinline__ void ldsm_x4(uint32_t* r, uint32_t addr) {
    asm volatile("ldmatrix.sync.aligned.m8n8.x4.shared.b16 {%0,%1,%2,%3}, [%4];"
                 : "=r"(r[0]), "=r"(r[1]), "=r"(r[2]), "=r"(r[3]) : "r"(addr));
}
__device__ __forceinline__ void mma16816(float* c, const uint32_t* a,
                                         const uint32_t* b) {
    asm volatile(
        "mma.sync.aligned.m16n8k16.row.col.f32.bf16.bf16.f32 "
        "{%0,%1,%2,%3}, {%4,%5,%6,%7}, {%8,%9}, {%0,%1,%2,%3};"
        : "+f"(c[0]), "+f"(c[1]), "+f"(c[2]), "+f"(c[3])
        : "r"(a[0]), "r"(a[1]), "r"(a[2]), "r"(a[3]), "r"(b[0]), "r"(b[1]));
}
#define SW128(o) ((o) ^ (((o) >> 3) & 0x70))

// ---------------------------------------------------------------------------
// Split kernels: fp32 -> (hi, lo) bf16
// ---------------------------------------------------------------------------
__global__ __launch_bounds__(256) void split_kernel(
    const float4* __restrict__ x, __nv_bfloat162* __restrict__ hi,
    __nv_bfloat162* __restrict__ lo, int n4)
{
    int i = blockIdx.x * 256 + threadIdx.x;
    if (i >= n4) return;
    float4 v = x[i];
    __nv_bfloat16 h0 = __float2bfloat16(v.x);
    __nv_bfloat16 h1 = __float2bfloat16(v.y);
    __nv_bfloat16 h2 = __float2bfloat16(v.z);
    __nv_bfloat16 h3 = __float2bfloat16(v.w);
    __nv_bfloat16 l0 = __float2bfloat16(v.x - __bfloat162float(h0));
    __nv_bfloat16 l1 = __float2bfloat16(v.y - __bfloat162float(h1));
    __nv_bfloat16 l2 = __float2bfloat16(v.z - __bfloat162float(h2));
    __nv_bfloat16 l3 = __float2bfloat16(v.w - __bfloat162float(h3));
    hi[2 * i]     = __halves2bfloat162(h0, h1);
    hi[2 * i + 1] = __halves2bfloat162(h2, h3);
    lo[2 * i]     = __halves2bfloat162(l0, l1);
    lo[2 * i + 1] = __halves2bfloat162(l2, l3);
}

// W[K][N] fp32  ->  T_hi/T_lo [N][K] bf16 (transpose + split)
__global__ __launch_bounds__(256) void wsplit_kernel(
    const float* __restrict__ W, __nv_bfloat16* __restrict__ Thi,
    __nv_bfloat16* __restrict__ Tlo)
{
    __shared__ float t[32][33];
    const int bn = blockIdx.x * 32;
    const int bk = blockIdx.y * 32;
    const int x  = threadIdx.x & 31;
    const int y4 = (threadIdx.x >> 5) * 4;
#pragma unroll
    for (int j = 0; j < 4; j++)
        t[y4 + j][x] = W[(size_t)(bk + y4 + j) * DM + bn + x];
    __syncthreads();
#pragma unroll
    for (int j = 0; j < 4; j++) {
        float v = t[x][y4 + j];
        __nv_bfloat16 h = __float2bfloat16(v);
        __nv_bfloat16 l = __float2bfloat16(v - __bfloat162float(h));
        size_t o = (size_t)(bn + y4 + j) * DM + bk + x;
        Thi[o] = h; Tlo[o] = l;
    }
}

// ---------------------------------------------------------------------------
// HMMA GEMM: C[M,N] = A[M,K] @ B^T[N,K] + bias, split-bf16 (3 mma chains).
// CTA tile 128x128, K-tile 64, cp.async double buffer, mma.sync m16n8k16.
// ---------------------------------------------------------------------------
#define TM 128
#define TN 128
#define TK 64
#define KTILES (DM / TK)        // 16
#define SUBTILE 16384           // 128 rows * 128B
#define BUFSZ   (4 * SUBTILE)   // Ahi, Alo, Bhi, Blo  (64 KB)
#define GSMEM   (1024 + 2 * BUFSZ)

__device__ __forceinline__ void issue_tile(
    uint32_t bufaddr,
    const __nv_bfloat16* gAh, const __nv_bfloat16* gAl,
    const __nv_bfloat16* gBh, const __nv_bfloat16* gBl, int tid)
{
    const __nv_bfloat16* gs[4] = {gAh, gAl, gBh, gBl};
#pragma unroll
    for (int s = 0; s < 4; s++) {
        uint32_t dst = bufaddr + s * SUBTILE;
        const __nv_bfloat16* g = gs[s];
#pragma unroll
        for (int it = 0; it < 4; it++) {
            int c = tid + it * 256;          // 0..1023 16B chunks
            int row = c >> 3, col = c & 7;
            uint32_t bo = (uint32_t)(row * 128 + col * 16);
            cpa16(dst + SW128(bo), g + (size_t)row * DM + col * 8);
        }
    }
}

__global__ __launch_bounds__(256) void gemm_tc_kernel(
    const __nv_bfloat16* __restrict__ Ahi, const __nv_bfloat16* __restrict__ Alo,
    const __nv_bfloat16* __restrict__ Bhi, const __nv_bfloat16* __restrict__ Blo,
    const float* __restrict__ bias, float* __restrict__ C)
{
    extern __shared__ char smraw[];
    uint32_t sb0   = smem_u32(smraw);
    uint32_t sbase = (sb0 + 1023u) & ~1023u;      // 1024-aligned for SW128

    const int tid  = threadIdx.x;
    const int wid  = tid >> 5;
    const int lane = tid & 31;
    const int bm = blockIdx.y * TM;
    const int bn = blockIdx.x * TN;
    const int wm = (wid & 3) * 32;     // warp row base within tile
    const int wn = (wid >> 2) * 64;    // warp col base within tile

    const __nv_bfloat16* gAh = Ahi + (size_t)bm * DM;
    const __nv_bfloat16* gAl = Alo + (size_t)bm * DM;
    const __nv_bfloat16* gBh = Bhi + (size_t)bn * DM;
    const __nv_bfloat16* gBl = Blo + (size_t)bn * DM;

    // --- per-thread ldmatrix address components ---
    // swizzled addr = row*128 + (inrow_byte ^ ((row&7)<<4)); mask applied ONCE.
    const int sub = lane >> 3, rin = lane & 7;
    const int arow0 = wm + (sub & 1) * 8 + rin;
    const uint32_t aoff0 = (uint32_t)(arow0 * 128);          // rows i*16..
    const uint32_t aoff1 = (uint32_t)((arow0 + 16) * 128);
    const uint32_t amask = (uint32_t)(arow0 & 7) << 4;       // (row+16)&7 == row&7
    const uint32_t akadd = (uint32_t)(sub >> 1) * 16;
    const int brow0 = wn + (sub >> 1) * 8 + rin;
    const uint32_t bmask = (uint32_t)(brow0 & 7) << 4;       // jp*16 keeps low 3 bits
    const uint32_t bkadd = (uint32_t)(sub & 1) * 16;

    float acc[2][8][4];
#pragma unroll
    for (int i = 0; i < 2; i++)
#pragma unroll
        for (int j = 0; j < 8; j++)
#pragma unroll
            for (int c = 0; c < 4; c++) acc[i][j][c] = 0.f;

    // --- prologue: tile 0 ---
    issue_tile(sbase, gAh, gAl, gBh, gBl, tid);
    CP_COMMIT();

    for (int t = 0; t < KTILES; t++) {
        const uint32_t buf = sbase + (uint32_t)(t & 1) * BUFSZ;
        if (t + 1 < KTILES) {
            const int ko = (t + 1) * TK;
            issue_tile(sbase + (uint32_t)((t + 1) & 1) * BUFSZ,
                       gAh + ko, gAl + ko, gBh + ko, gBl + ko, tid);
            CP_COMMIT();
            CP_WAIT(1);
        } else {
            CP_WAIT(0);
        }
        __syncthreads();

        const uint32_t aHi = buf;
        const uint32_t aLo = buf + SUBTILE;
        const uint32_t bHi = buf + 2 * SUBTILE;
        const uint32_t bLo = buf + 3 * SUBTILE;

#pragma unroll
        for (int ks = 0; ks < 4; ks++) {
            const uint32_t kb = (uint32_t)ks * 32;      // k16 = 32 bytes
            const uint32_t aIn = (kb + akadd) ^ amask;
            const uint32_t bIn = (kb + bkadd) ^ bmask;
            uint32_t ah[2][4], al[2][4];
            ldsm_x4(ah[0], aHi + aoff0 + aIn);
            ldsm_x4(ah[1], aHi + aoff1 + aIn);
            ldsm_x4(al[0], aLo + aoff0 + aIn);
            ldsm_x4(al[1], aLo + aoff1 + aIn);
#pragma unroll
            for (int jp = 0; jp < 4; jp++) {
                const uint32_t boff = (uint32_t)((brow0 + jp * 16) * 128);
                uint32_t bh[4], bl[4];
                ldsm_x4(bh, bHi + boff + bIn);
                ldsm_x4(bl, bLo + boff + bIn);
#pragma unroll
                for (int i = 0; i < 2; i++) {
#pragma unroll
                    for (int jj = 0; jj < 2; jj++) {
                        float* c = acc[i][jp * 2 + jj];
                        mma16816(c, ah[i], bh + jj * 2);
                        mma16816(c, ah[i], bl + jj * 2);
                        mma16816(c, al[i], bh + jj * 2);
                    }
                }
            }
        }
        __syncthreads();
    }

    // --- epilogue: bias + store ---
    const int g4 = lane >> 2, l4 = lane & 3;
#pragma unroll
    for (int i = 0; i < 2; i++) {
        const int row = bm + wm + i * 16 + g4;
#pragma unroll
        for (int j = 0; j < 8; j++) {
            const int col = bn + wn + j * 8 + l4 * 2;
            const float b0 = bias[col], b1 = bias[col + 1];
            float2 o0, o1;
            o0.x = acc[i][j][0] + b0; o0.y = acc[i][j][1] + b1;
            o1.x = acc[i][j][2] + b0; o1.y = acc[i][j][3] + b1;
            *(float2*)&C[(size_t)row * DM + col]       = o0;
            *(float2*)&C[(size_t)(row + 8) * DM + col] = o1;
        }
    }
}

// ---------------------------------------------------------------------------
// Flash attention v2 (fp32, register-blocked) — unchanged.
// ---------------------------------------------------------------------------
#define QT   128
#define CT   64
#define QPAD 4
#define QST  (QT + QPAD)
#define KST  (CT + QPAD)
#define VST  (DK + 8)

__global__ __launch_bounds__(256) void attn_kernel(
    const float* __restrict__ Q, const float* __restrict__ K,
    const float* __restrict__ V, float* __restrict__ O)
{
    extern __shared__ float smf[];
    float (*QsT)[QST] = (float(*)[QST])(smf);
    float (*KsT)[KST] = (float(*)[KST])(smf + DK * QST);
    float (*Vs) [VST] = (float(*)[VST])(smf + DK * QST + DK * KST);
    float (*PsT)[QST] = (float(*)[QST])(smf + DK * QST + DK * KST + CT * VST);

    const int tid = threadIdx.x;
    const int tx = tid & 15;
    const int ty = tid >> 4;
    const int R  = ty * 8;
    const int C4 = tx * 4;

    const int b  = blockIdx.z;
    const int h  = blockIdx.y;
    const int qt = blockIdx.x;

    const float* Qb = Q + (size_t)(b * SEQ + qt * QT) * DM + h * DK;
    const float* Kb = K + (size_t)b * SEQ * DM + h * DK;
    const float* Vb = V + (size_t)b * SEQ * DM + h * DK;

    {
        const int r  = tid >> 1;
        const int kh = (tid & 1) * 32;
        const float4* src = (const float4*)&Qb[(size_t)r * DM + kh];
#pragma unroll
        for (int j = 0; j < 8; j++) {
            float4 v = src[j];
            QsT[kh + j * 4 + 0][r] = v.x * 0.125f;
            QsT[kh + j * 4 + 1][r] = v.y * 0.125f;
            QsT[kh + j * 4 + 2][r] = v.z * 0.125f;
            QsT[kh + j * 4 + 3][r] = v.w * 0.125f;
        }
    }

    float m_i[8], l_i[8], o_acc[8][4];
#pragma unroll
    for (int i = 0; i < 8; i++) {
        m_i[i] = -INFINITY; l_i[i] = 0.f;
#pragma unroll
        for (int j = 0; j < 4; j++) o_acc[i][j] = 0.f;
    }

    for (int t = 0; t < SEQ / CT; t++) {
        __syncthreads();
        {
            const int r  = tid >> 2;
            const int ko = (tid & 3) * 16;
            const float4* ks = (const float4*)&Kb[(size_t)(t * CT + r) * DM + ko];
            const float4* vs = (const float4*)&Vb[(size_t)(t * CT + r) * DM + ko];
#pragma unroll
            for (int j = 0; j < 4; j++) {
                float4 kv = ks[j];
                KsT[ko + j * 4 + 0][r] = kv.x;
                KsT[ko + j * 4 + 1][r] = kv.y;
                KsT[ko + j * 4 + 2][r] = kv.z;
                KsT[ko + j * 4 + 3][r] = kv.w;
                *(float4*)&Vs[r][ko + j * 4] = vs[j];
            }
        }
        __syncthreads();

        float s[8][4];
#pragma unroll
        for (int i = 0; i < 8; i++)
#pragma unroll
            for (int j = 0; j < 4; j++) s[i][j] = 0.f;

#pragma unroll 16
        for (int k = 0; k < DK; k++) {
            float a[8], bb[4];
            *(float4*)&a[0] = *(float4*)&QsT[k][R];
            *(float4*)&a[4] = *(float4*)&QsT[k][R + 4];
            *(float4*)&bb[0] = *(float4*)&KsT[k][C4];
#pragma unroll
            for (int i = 0; i < 8; i++)
#pragma unroll
                for (int j = 0; j < 4; j++)
                    s[i][j] = fmaf(a[i], bb[j], s[i][j]);
        }

#pragma unroll
        for (int i = 0; i < 8; i++) {
            float mt = fmaxf(fmaxf(s[i][0], s[i][1]), fmaxf(s[i][2], s[i][3]));
            mt = fmaxf(mt, __shfl_xor_sync(0xffffffffu, mt, 1));
            mt = fmaxf(mt, __shfl_xor_sync(0xffffffffu, mt, 2));
            mt = fmaxf(mt, __shfl_xor_sync(0xffffffffu, mt, 4));
            mt = fmaxf(mt, __shfl_xor_sync(0xffffffffu, mt, 8));
            const float m_new = fmaxf(m_i[i], mt);
            const float corr  = __expf(m_i[i] - m_new);
            float ps = 0.f;
#pragma unroll
            for (int j = 0; j < 4; j++) {
                s[i][j] = __expf(s[i][j] - m_new);
                ps += s[i][j];
            }
            ps += __shfl_xor_sync(0xffffffffu, ps, 1);
            ps += __shfl_xor_sync(0xffffffffu, ps, 2);
            ps += __shfl_xor_sync(0xffffffffu, ps, 4);
            ps += __shfl_xor_sync(0xffffffffu, ps, 8);
            l_i[i] = l_i[i] * corr + ps;
            m_i[i] = m_new;
#pragma unroll
            for (int j = 0; j < 4; j++) o_acc[i][j] *= corr;
        }

#pragma unroll
        for (int j = 0; j < 4; j++) {
            float4 p0 = make_float4(s[0][j], s[1][j], s[2][j], s[3][j]);
            float4 p1 = make_float4(s[4][j], s[5][j], s[6][j], s[7][j]);
            *(float4*)&PsT[C4 + j][R]     = p0;
            *(float4*)&PsT[C4 + j][R + 4] = p1;
        }
        __syncthreads();

#pragma unroll 16
        for (int c = 0; c < CT; c++) {
            float a[8], bb[4];
            *(float4*)&a[0] = *(float4*)&PsT[c][R];
            *(float4*)&a[4] = *(float4*)&PsT[c][R + 4];
            *(float4*)&bb[0] = *(float4*)&Vs[c][C4];
#pragma unroll
            for (int i = 0; i < 8; i++)
#pragma unroll
                for (int j = 0; j < 4; j++)
                    o_acc[i][j] = fmaf(a[i], bb[j], o_acc[i][j]);
        }
    }

#pragma unroll
    for (int i = 0; i < 8; i++) {
        const float inv = 1.f / l_i[i];
        float4 o;
        o.x = o_acc[i][0] * inv; o.y = o_acc[i][1] * inv;
        o.z = o_acc[i][2] * inv; o.w = o_acc[i][3] * inv;
        float* Ob = O + (size_t)(b * SEQ + qt * QT + R + i) * DM + h * DK + C4;
        *(float4*)&Ob[0] = o;
    }
}

// ---------------------------------------------------------------------------
extern "C" void kernel_launch(void* const* d_in, const int* in_sizes, int n_in,
                              void* d_out, int out_size)
{
    const float* q  = (const float*)d_in[0];
    const float* k  = (const float*)d_in[1];
    const float* v  = (const float*)d_in[2];
    const float* wq = (const float*)d_in[3];
    const float* bq = (const float*)d_in[4];
    const float* wk = (const float*)d_in[5];
    const float* bk = (const float*)d_in[6];
    const float* wv = (const float*)d_in[7];
    const float* bv = (const float*)d_in[8];
    const float* wo = (const float*)d_in[9];
    const float* bo = (const float*)d_in[10];
    float* out = (float*)d_out;

    float *qp, *kp, *vp, *ctx;
    __nv_bfloat16 *ahi, *alo, *bhi, *blo;
    cudaGetSymbolAddress((void**)&qp,  g_qp);
    cudaGetSymbolAddress((void**)&kp,  g_kp);
    cudaGetSymbolAddress((void**)&vp,  g_vp);
    cudaGetSymbolAddress((void**)&ctx, g_ctx);
    cudaGetSymbolAddress((void**)&ahi, g_ahi);
    cudaGetSymbolAddress((void**)&alo, g_alo);
    cudaGetSymbolAddress((void**)&bhi, g_bhi);
    cudaGetSymbolAddress((void**)&blo, g_blo);

    cudaFuncSetAttribute(gemm_tc_kernel,
                         cudaFuncAttributeMaxDynamicSharedMemorySize, GSMEM);

    const int n4 = MTOT * DM / 4;
    const dim3 sgrid(n4 / 256);
    const dim3 wgrid(32, 32);
    const dim3 ggrid(DM / TN, MTOT / TM);   // (8, 64)

    // Q projection
    wsplit_kernel<<<wgrid, 256>>>(wq, bhi, blo);
    split_kernel<<<sgrid, 256>>>((const float4*)q,
        (__nv_bfloat162*)ahi, (__nv_bfloat162*)alo, n4);
    gemm_tc_kernel<<<ggrid, 256, GSMEM>>>(ahi, alo, bhi, blo, bq, qp);
    // K projection
    wsplit_kernel<<<wgrid, 256>>>(wk, bhi, blo);
    split_kernel<<<sgrid, 256>>>((const float4*)k,
        (__nv_bfloat162*)ahi, (__nv_bfloat162*)alo, n4);
    gemm_tc_kernel<<<ggrid, 256, GSMEM>>>(ahi, alo, bhi, blo, bk, kp);
    // V projection
    wsplit_kernel<<<wgrid, 256>>>(wv, bhi, blo);
    split_kernel<<<sgrid, 256>>>((const float4*)v,
        (__nv_bfloat162*)ahi, (__nv_bfloat162*)alo, n4);
    gemm_tc_kernel<<<ggrid, 256, GSMEM>>>(ahi, alo, bhi, blo, bv, vp);

    // attention
    const int smem_attn =
        (DK * QST + DK * KST + CT * VST + CT * QST) * (int)sizeof(float);
    cudaFuncSetAttribute(attn_kernel,
                         cudaFuncAttributeMaxDynamicSharedMemorySize, smem_attn);
    const dim3 agrid(SEQ / QT, NH, BS);
    attn_kernel<<<agrid, 256, smem_attn>>>(qp, kp, vp, ctx);

    // output projection
    wsplit_kernel<<<wgrid, 256>>>(wo, bhi, blo);
    split_kernel<<<sgrid, 256>>>((const float4*)ctx,
        (__nv_bfloat162*)ahi, (__nv_bfloat162*)alo, n4);
    gemm_tc_kernel<<<ggrid, 256, GSMEM>>>(ahi, alo, bhi, blo, bo, out);
}

// round 11
// speedup vs baseline: 8.6173x; 1.9889x over previous
#include <cuda_runtime.h>
#include <cuda_bf16.h>
#include <math.h>
#include <stdint.h>

#define BS   4
#define SEQ  2048
#define DM   1024
#define NH   16
#define DK   64
#define MTOT (BS * SEQ)   // 8192

// ---------------- scratch (device globals; no allocation allowed) ----------
__device__ __nv_bfloat16 g_qhi[MTOT * DM];
__device__ __nv_bfloat16 g_qlo[MTOT * DM];
__device__ __nv_bfloat16 g_khi[MTOT * DM];
__device__ __nv_bfloat16 g_klo[MTOT * DM];
__device__ __nv_bfloat16 g_vhi[MTOT * DM];
__device__ __nv_bfloat16 g_vlo[MTOT * DM];
__device__ __nv_bfloat16 g_chi[MTOT * DM];
__device__ __nv_bfloat16 g_clo[MTOT * DM];
__device__ __nv_bfloat16 g_ahi[MTOT * DM];
__device__ __nv_bfloat16 g_alo[MTOT * DM];
__device__ __nv_bfloat16 g_bhi[DM * DM];
__device__ __nv_bfloat16 g_blo[DM * DM];

// ---------------- helpers ---------------------------------------------------
__device__ __forceinline__ uint32_t smem_u32(const void* p) {
    uint32_t a;
    asm("{ .reg .u64 t; cvta.to.shared.u64 t, %1; cvt.u32.u64 %0, t; }"
        : "=r"(a) : "l"(p));
    return a;
}
__device__ __forceinline__ void cpa16(uint32_t dst, const void* src) {
    asm volatile("cp.async.cg.shared.global [%0], [%1], 16;"
                 :: "r"(dst), "l"(src));
}
#define CP_COMMIT() asm volatile("cp.async.commit_group;" ::: "memory")
#define CP_WAIT(n)  asm volatile("cp.async.wait_group %0;" :: "n"(n) : "memory")

__device__ __forceinline__ void ldsm_x4(uint32_t* r, uint32_t addr) {
    asm volatile("ldmatrix.sync.aligned.m8n8.x4.shared.b16 {%0,%1,%2,%3}, [%4];"
                 : "=r"(r[0]), "=r"(r[1]), "=r"(r[2]), "=r"(r[3]) : "r"(addr));
}
__device__ __forceinline__ void ldsm_x4_t(uint32_t* r, uint32_t addr) {
    asm volatile("ldmatrix.sync.aligned.m8n8.x4.trans.shared.b16 {%0,%1,%2,%3}, [%4];"
                 : "=r"(r[0]), "=r"(r[1]), "=r"(r[2]), "=r"(r[3]) : "r"(addr));
}
__device__ __forceinline__ void mma16816(float* c, const uint32_t* a,
                                         const uint32_t* b) {
    asm volatile(
        "mma.sync.aligned.m16n8k16.row.col.f32.bf16.bf16.f32 "
        "{%0,%1,%2,%3}, {%4,%5,%6,%7}, {%8,%9}, {%0,%1,%2,%3};"
        : "+f"(c[0]), "+f"(c[1]), "+f"(c[2]), "+f"(c[3])
        : "r"(a[0]), "r"(a[1]), "r"(a[2]), "r"(a[3]), "r"(b[0]), "r"(b[1]));
}
// pack {lo, hi} floats into bf16x2 (lower half = lo)
__device__ __forceinline__ uint32_t pk(float lo, float hi) {
    uint32_t d;
    asm("cvt.rn.bf16x2.f32 %0, %1, %2;" : "=r"(d) : "f"(hi), "f"(lo));
    return d;
}
__device__ __forceinline__ float lo_f(uint32_t d) { return __uint_as_float(d << 16); }
__device__ __forceinline__ float hi_f(uint32_t d) { return __uint_as_float(d & 0xffff0000u); }
#define SW128(o) ((o) ^ (((o) >> 3) & 0x70))

// ---------------------------------------------------------------------------
// Split kernels: fp32 -> (hi, lo) bf16
// ---------------------------------------------------------------------------
__global__ __launch_bounds__(256) void split_kernel(
    const float4* __restrict__ x, __nv_bfloat162* __restrict__ hi,
    __nv_bfloat162* __restrict__ lo, int n4)
{
    int i = blockIdx.x * 256 + threadIdx.x;
    if (i >= n4) return;
    float4 v = x[i];
    uint32_t h0 = pk(v.x, v.y), h1 = pk(v.z, v.w);
    uint32_t l0 = pk(v.x - lo_f(h0), v.y - hi_f(h0));
    uint32_t l1 = pk(v.z - lo_f(h1), v.w - hi_f(h1));
    ((uint32_t*)hi)[2 * i]     = h0;
    ((uint32_t*)hi)[2 * i + 1] = h1;
    ((uint32_t*)lo)[2 * i]     = l0;
    ((uint32_t*)lo)[2 * i + 1] = l1;
}

// W[K][N] fp32  ->  T_hi/T_lo [N][K] bf16 (transpose + split)
__global__ __launch_bounds__(256) void wsplit_kernel(
    const float* __restrict__ W, __nv_bfloat16* __restrict__ Thi,
    __nv_bfloat16* __restrict__ Tlo)
{
    __shared__ float t[32][33];
    const int bn = blockIdx.x * 32;
    const int bk = blockIdx.y * 32;
    const int x  = threadIdx.x & 31;
    const int y4 = (threadIdx.x >> 5) * 4;
#pragma unroll
    for (int j = 0; j < 4; j++)
        t[y4 + j][x] = W[(size_t)(bk + y4 + j) * DM + bn + x];
    __syncthreads();
#pragma unroll
    for (int j = 0; j < 4; j++) {
        float v = t[x][y4 + j];
        __nv_bfloat16 h = __float2bfloat16(v);
        __nv_bfloat16 l = __float2bfloat16(v - __bfloat162float(h));
        size_t o = (size_t)(bn + y4 + j) * DM + bk + x;
        Thi[o] = h; Tlo[o] = l;
    }
}

// ---------------------------------------------------------------------------
// HMMA GEMM: C = A[M,K] @ B^T[N,K] + bias (then * scale), split-bf16.
// Output: fp32 (Cf != null) or split hi/lo bf16.
// ---------------------------------------------------------------------------
#define TM 128
#define TN 128
#define TK 64
#define KTILES (DM / TK)        // 16
#define SUBTILE 16384           // 128 rows * 128B
#define BUFSZ   (4 * SUBTILE)
#define GSMEM   (1024 + 2 * BUFSZ)

__device__ __forceinline__ void issue_tile(
    uint32_t bufaddr,
    const __nv_bfloat16* gAh, const __nv_bfloat16* gAl,
    const __nv_bfloat16* gBh, const __nv_bfloat16* gBl, int tid)
{
    const __nv_bfloat16* gs[4] = {gAh, gAl, gBh, gBl};
#pragma unroll
    for (int s = 0; s < 4; s++) {
        uint32_t dst = bufaddr + s * SUBTILE;
        const __nv_bfloat16* g = gs[s];
#pragma unroll
        for (int it = 0; it < 4; it++) {
            int c = tid + it * 256;
            int row = c >> 3, col = c & 7;
            uint32_t bo = (uint32_t)(row * 128 + col * 16);
            cpa16(dst + SW128(bo), g + (size_t)row * DM + col * 8);
        }
    }
}

__global__ __launch_bounds__(256) void gemm_tc_kernel(
    const __nv_bfloat16* __restrict__ Ahi, const __nv_bfloat16* __restrict__ Alo,
    const __nv_bfloat16* __restrict__ Bhi, const __nv_bfloat16* __restrict__ Blo,
    const float* __restrict__ bias, float* __restrict__ Cf,
    __nv_bfloat16* __restrict__ Chi, __nv_bfloat16* __restrict__ Clo,
    float scale)
{
    extern __shared__ char smraw[];
    uint32_t sb0   = smem_u32(smraw);
    uint32_t sbase = (sb0 + 1023u) & ~1023u;

    const int tid  = threadIdx.x;
    const int wid  = tid >> 5;
    const int lane = tid & 31;
    const int bm = blockIdx.y * TM;
    const int bn = blockIdx.x * TN;
    const int wm = (wid & 3) * 32;
    const int wn = (wid >> 2) * 64;

    const __nv_bfloat16* gAh = Ahi + (size_t)bm * DM;
    const __nv_bfloat16* gAl = Alo + (size_t)bm * DM;
    const __nv_bfloat16* gBh = Bhi + (size_t)bn * DM;
    const __nv_bfloat16* gBl = Blo + (size_t)bn * DM;

    const int sub = lane >> 3, rin = lane & 7;
    const int arow0 = wm + (sub & 1) * 8 + rin;
    const uint32_t aoff0 = (uint32_t)(arow0 * 128);
    const uint32_t aoff1 = (uint32_t)((arow0 + 16) * 128);
    const uint32_t amask = (uint32_t)(arow0 & 7) << 4;
    const uint32_t akadd = (uint32_t)(sub >> 1) * 16;
    const int brow0 = wn + (sub >> 1) * 8 + rin;
    const uint32_t bmask = (uint32_t)(brow0 & 7) << 4;
    const uint32_t bkadd = (uint32_t)(sub & 1) * 16;

    float acc[2][8][4];
#pragma unroll
    for (int i = 0; i < 2; i++)
#pragma unroll
        for (int j = 0; j < 8; j++)
#pragma unroll
            for (int c = 0; c < 4; c++) acc[i][j][c] = 0.f;

    issue_tile(sbase, gAh, gAl, gBh, gBl, tid);
    CP_COMMIT();

    for (int t = 0; t < KTILES; t++) {
        const uint32_t buf = sbase + (uint32_t)(t & 1) * BUFSZ;
        if (t + 1 < KTILES) {
            const int ko = (t + 1) * TK;
            issue_tile(sbase + (uint32_t)((t + 1) & 1) * BUFSZ,
                       gAh + ko, gAl + ko, gBh + ko, gBl + ko, tid);
            CP_COMMIT();
            CP_WAIT(1);
        } else {
            CP_WAIT(0);
        }
        __syncthreads();

        const uint32_t aHi = buf;
        const uint32_t aLo = buf + SUBTILE;
        const uint32_t bHi = buf + 2 * SUBTILE;
        const uint32_t bLo = buf + 3 * SUBTILE;

#pragma unroll
        for (int ks = 0; ks < 4; ks++) {
            const uint32_t kb = (uint32_t)ks * 32;
            const uint32_t aIn = (kb + akadd) ^ amask;
            const uint32_t bIn = (kb + bkadd) ^ bmask;
            uint32_t ah[2][4], al[2][4];
            ldsm_x4(ah[0], aHi + aoff0 + aIn);
            ldsm_x4(ah[1], aHi + aoff1 + aIn);
            ldsm_x4(al[0], aLo + aoff0 + aIn);
            ldsm_x4(al[1], aLo + aoff1 + aIn);
#pragma unroll
            for (int jp = 0; jp < 4; jp++) {
                const uint32_t boff = (uint32_t)((brow0 + jp * 16) * 128);
                uint32_t bh[4], bl[4];
                ldsm_x4(bh, bHi + boff + bIn);
                ldsm_x4(bl, bLo + boff + bIn);
#pragma unroll
                for (int i = 0; i < 2; i++) {
#pragma unroll
                    for (int jj = 0; jj < 2; jj++) {
                        float* c = acc[i][jp * 2 + jj];
                        mma16816(c, ah[i], bh + jj * 2);
                        mma16816(c, ah[i], bl + jj * 2);
                        mma16816(c, al[i], bh + jj * 2);
                    }
                }
            }
        }
        __syncthreads();
    }

    // --- epilogue ---
    const int g4 = lane >> 2, l4 = lane & 3;
#pragma unroll
    for (int i = 0; i < 2; i++) {
        const int row = bm + wm + i * 16 + g4;
#pragma unroll
        for (int j = 0; j < 8; j++) {
            const int col = bn + wn + j * 8 + l4 * 2;
            const float b0 = bias[col], b1 = bias[col + 1];
            float o0 = (acc[i][j][0] + b0) * scale;
            float o1 = (acc[i][j][1] + b1) * scale;
            float o2 = (acc[i][j][2] + b0) * scale;
            float o3 = (acc[i][j][3] + b1) * scale;
            if (Cf) {
                *(float2*)&Cf[(size_t)row * DM + col]       = make_float2(o0, o1);
                *(float2*)&Cf[(size_t)(row + 8) * DM + col] = make_float2(o2, o3);
            } else {
                uint32_t h0 = pk(o0, o1);
                uint32_t l0 = pk(o0 - lo_f(h0), o1 - hi_f(h0));
                uint32_t h1 = pk(o2, o3);
                uint32_t l1 = pk(o2 - lo_f(h1), o3 - hi_f(h1));
                *(uint32_t*)&Chi[(size_t)row * DM + col]       = h0;
                *(uint32_t*)&Clo[(size_t)row * DM + col]       = l0;
                *(uint32_t*)&Chi[(size_t)(row + 8) * DM + col] = h1;
                *(uint32_t*)&Clo[(size_t)(row + 8) * DM + col] = l1;
            }
        }
    }
}

// ---------------------------------------------------------------------------
// Flash attention on HMMA, split-bf16 Q/K/V/P.
// CTA = (b, h, 128 q-rows); 8 warps x 16 q-rows; KV tiles of 64, double buffer.
// ---------------------------------------------------------------------------
#define ACT    64
#define NKVT   (SEQ / ACT)      // 32
#define SQH    0
#define SQL    16384
#define SKV    32768            // per-buffer: KH,KL,VH,VL each 8192
#define AKVBUF 32768
#define A_SMEM (1024 + SKV + 2 * AKVBUF)   // 1KB align slack + 96KB

__device__ __forceinline__ void issue_kv(
    uint32_t dst,
    const __nv_bfloat16* Kh, const __nv_bfloat16* Kl,
    const __nv_bfloat16* Vh, const __nv_bfloat16* Vl,
    size_t grow, int hoff, int tid)
{
    const __nv_bfloat16* gs[4] = {Kh, Kl, Vh, Vl};
#pragma unroll
    for (int s = 0; s < 4; s++) {
        const __nv_bfloat16* g = gs[s] + grow * DM + hoff;
#pragma unroll
        for (int it = 0; it < 2; it++) {
            int c = tid + it * 256;          // 0..511
            int r = c >> 3, cc = c & 7;
            uint32_t bo = SW128((uint32_t)(r * 128 + cc * 16));
            cpa16(dst + s * 8192 + bo, g + (size_t)r * DM + cc * 8);
        }
    }
}

__global__ __launch_bounds__(256, 1) void attn_tc_kernel(
    const __nv_bfloat16* __restrict__ Qh, const __nv_bfloat16* __restrict__ Ql,
    const __nv_bfloat16* __restrict__ Kh, const __nv_bfloat16* __restrict__ Kl,
    const __nv_bfloat16* __restrict__ Vh, const __nv_bfloat16* __restrict__ Vl,
    __nv_bfloat16* __restrict__ Ch, __nv_bfloat16* __restrict__ Cl)
{
    extern __shared__ char smraw[];
    uint32_t sb0   = smem_u32(smraw);
    uint32_t sbase = (sb0 + 1023u) & ~1023u;

    const int tid = threadIdx.x, wid = tid >> 5, lane = tid & 31;
    const int b = blockIdx.z, h = blockIdx.y, qt = blockIdx.x;
    const size_t row0   = (size_t)(b * SEQ + qt * 128);
    const size_t kvrow0 = (size_t)b * SEQ;
    const int hoff = h * DK;

    // ---- load Q hi/lo (16KB each) ----
#pragma unroll
    for (int it = 0; it < 4; it++) {
        int c = tid + it * 256;              // 0..1023
        int r = c >> 3, cc = c & 7;
        uint32_t bo = SW128((uint32_t)(r * 128 + cc * 16));
        cpa16(sbase + SQH + bo, Qh + (row0 + r) * DM + hoff + cc * 8);
        cpa16(sbase + SQL + bo, Ql + (row0 + r) * DM + hoff + cc * 8);
    }
    issue_kv(sbase + SKV, Kh, Kl, Vh, Vl, kvrow0, hoff, tid);
    CP_COMMIT();                             // group0: Q + KV0

    // ---- per-lane fragment address components ----
    const int sub = lane >> 3, rin = lane & 7;
    const uint32_t xm = (uint32_t)rin << 4;                 // swizzle mask
    // A (Q / warp rows): rows wid*16 + (sub&1)*8 + rin
    const uint32_t a_row = (uint32_t)((wid * 16 + (sub & 1) * 8 + rin) * 128);
    const uint32_t a_byte = (uint32_t)(sub >> 1) * 16;
    // K B-frag: rows (sub>>1)*8 + rin (+ 8*jb), bytes (sub&1)*16 (+ ks*32)
    const uint32_t k_row = (uint32_t)(((sub >> 1) * 8 + rin) * 128);
    const uint32_t k_byte = (uint32_t)(sub & 1) * 16;
    // V trans frag: rows (sub&1)*8 + rin (+ 16*kb), bytes (sub>>1)*16 (+ 16*jb)
    const uint32_t v_row = (uint32_t)(((sub & 1) * 8 + rin) * 128);
    const uint32_t v_byte = (uint32_t)(sub >> 1) * 16;

    float oA[8][4];
#pragma unroll
    for (int j = 0; j < 8; j++)
#pragma unroll
        for (int c = 0; c < 4; c++) oA[j][c] = 0.f;
    float m0 = -INFINITY, m1 = -INFINITY, lsum0 = 0.f, lsum1 = 0.f;

    for (int t = 0; t < NKVT; t++) {
        const uint32_t buf = sbase + SKV + (uint32_t)(t & 1) * AKVBUF;
        if (t + 1 < NKVT) {
            issue_kv(sbase + SKV + (uint32_t)((t + 1) & 1) * AKVBUF,
                     Kh, Kl, Vh, Vl, kvrow0 + (size_t)(t + 1) * ACT, hoff, tid);
            CP_COMMIT();
            CP_WAIT(1);
        } else {
            CP_WAIT(0);
        }
        __syncthreads();

        const uint32_t bKH = buf, bKL = buf + 8192;
        const uint32_t bVH = buf + 16384, bVL = buf + 24576;

        // ---- S = Q K^T (3 products), fp32 accum ----
        float sA[8][4];
#pragma unroll
        for (int j = 0; j < 8; j++)
#pragma unroll
            for (int c = 0; c < 4; c++) sA[j][c] = 0.f;

#pragma unroll
        for (int ks = 0; ks < 4; ks++) {
            const uint32_t aIn = ((uint32_t)ks * 32 + a_byte) ^ xm;
            const uint32_t kIn = ((uint32_t)ks * 32 + k_byte) ^ xm;
            uint32_t qh[4], ql[4], kf[16];
            ldsm_x4(qh, sbase + SQH + a_row + aIn);
            ldsm_x4(ql, sbase + SQL + a_row + aIn);
#pragma unroll
            for (int jb = 0; jb < 8; jb += 2)
                ldsm_x4(kf + jb * 2, bKH + (uint32_t)jb * 1024 + k_row + kIn);
#pragma unroll
            for (int j = 0; j < 8; j++) {
                mma16816(sA[j], qh, kf + 2 * j);
                mma16816(sA[j], ql, kf + 2 * j);
            }
#pragma unroll
            for (int jb = 0; jb < 8; jb += 2)
                ldsm_x4(kf + jb * 2, bKL + (uint32_t)jb * 1024 + k_row + kIn);
#pragma unroll
            for (int j = 0; j < 8; j++)
                mma16816(sA[j], qh, kf + 2 * j);
        }

        // ---- online softmax (rows g4 and g4+8 per thread) ----
        float mt0 = -INFINITY, mt1 = -INFINITY;
#pragma unroll
        for (int j = 0; j < 8; j++) {
            mt0 = fmaxf(mt0, fmaxf(sA[j][0], sA[j][1]));
            mt1 = fmaxf(mt1, fmaxf(sA[j][2], sA[j][3]));
        }
        mt0 = fmaxf(mt0, __shfl_xor_sync(0xffffffffu, mt0, 1));
        mt0 = fmaxf(mt0, __shfl_xor_sync(0xffffffffu, mt0, 2));
        mt1 = fmaxf(mt1, __shfl_xor_sync(0xffffffffu, mt1, 1));
        mt1 = fmaxf(mt1, __shfl_xor_sync(0xffffffffu, mt1, 2));
        const float mn0 = fmaxf(m0, mt0), mn1 = fmaxf(m1, mt1);
        const float cr0 = __expf(m0 - mn0), cr1 = __expf(m1 - mn1);
        float ps0 = 0.f, ps1 = 0.f;
#pragma unroll
        for (int j = 0; j < 8; j++) {
            sA[j][0] = __expf(sA[j][0] - mn0); ps0 += sA[j][0];
            sA[j][1] = __expf(sA[j][1] - mn0); ps0 += sA[j][1];
            sA[j][2] = __expf(sA[j][2] - mn1); ps1 += sA[j][2];
            sA[j][3] = __expf(sA[j][3] - mn1); ps1 += sA[j][3];
        }
        ps0 += __shfl_xor_sync(0xffffffffu, ps0, 1);
        ps0 += __shfl_xor_sync(0xffffffffu, ps0, 2);
        ps1 += __shfl_xor_sync(0xffffffffu, ps1, 1);
        ps1 += __shfl_xor_sync(0xffffffffu, ps1, 2);
        lsum0 = lsum0 * cr0 + ps0;
        lsum1 = lsum1 * cr1 + ps1;
        m0 = mn0; m1 = mn1;
#pragma unroll
        for (int j = 0; j < 8; j++) {
            oA[j][0] *= cr0; oA[j][1] *= cr0;
            oA[j][2] *= cr1; oA[j][3] *= cr1;
        }

        // ---- O += P V (3 products); P frags built in registers ----
#pragma unroll
        for (int kb = 0; kb < 4; kb++) {
            const float* p0 = sA[2 * kb];
            const float* p1 = sA[2 * kb + 1];
            uint32_t pha[4], pla[4];
            pha[0] = pk(p0[0], p0[1]);
            pha[1] = pk(p0[2], p0[3]);
            pha[2] = pk(p1[0], p1[1]);
            pha[3] = pk(p1[2], p1[3]);
            pla[0] = pk(p0[0] - lo_f(pha[0]), p0[1] - hi_f(pha[0]));
            pla[1] = pk(p0[2] - lo_f(pha[1]), p0[3] - hi_f(pha[1]));
            pla[2] = pk(p1[0] - lo_f(pha[2]), p1[1] - hi_f(pha[2]));
            pla[3] = pk(p1[2] - lo_f(pha[3]), p1[3] - hi_f(pha[3]));
            const uint32_t vrow = (uint32_t)kb * 2048 + v_row;
#pragma unroll
            for (int jb = 0; jb < 8; jb += 2) {
                const uint32_t vIn = ((uint32_t)jb * 16 + v_byte) ^ xm;
                uint32_t vf[4];
                ldsm_x4_t(vf, bVH + vrow + vIn);
                mma16816(oA[jb],     pha, vf + 0);
                mma16816(oA[jb + 1], pha, vf + 2);
                mma16816(oA[jb],     pla, vf + 0);
                mma16816(oA[jb + 1], pla, vf + 2);
                ldsm_x4_t(vf, bVL + vrow + vIn);
                mma16816(oA[jb],     pha, vf + 0);
                mma16816(oA[jb + 1], pha, vf + 2);
            }
        }
        __syncthreads();
    }

    // ---- epilogue: normalize, split, store ctx hi/lo ----
    const float inv0 = 1.f / lsum0, inv1 = 1.f / lsum1;
    const size_t orow = row0 + wid * 16 + (lane >> 2);
    const int col = hoff + (lane & 3) * 2;
#pragma unroll
    for (int j = 0; j < 8; j++) {
        float o0 = oA[j][0] * inv0, o1 = oA[j][1] * inv0;
        float o2 = oA[j][2] * inv1, o3 = oA[j][3] * inv1;
        uint32_t h0 = pk(o0, o1);
        uint32_t l0 = pk(o0 - lo_f(h0), o1 - hi_f(h0));
        uint32_t h1 = pk(o2, o3);
        uint32_t l1 = pk(o2 - lo_f(h1), o3 - hi_f(h1));
        *(uint32_t*)&Ch[orow * DM + col + j * 8]       = h0;
        *(uint32_t*)&Cl[orow * DM + col + j * 8]       = l0;
        *(uint32_t*)&Ch[(orow + 8) * DM + col + j * 8] = h1;
        *(uint32_t*)&Cl[(orow + 8) * DM + col + j * 8] = l1;
    }
}

// ---------------------------------------------------------------------------
extern "C" void kernel_launch(void* const* d_in, const int* in_sizes, int n_in,
                              void* d_out, int out_size)
{
    const float* q  = (const float*)d_in[0];
    const float* k  = (const float*)d_in[1];
    const float* v  = (const float*)d_in[2];
    const float* wq = (const float*)d_in[3];
    const float* bq = (const float*)d_in[4];
    const float* wk = (const float*)d_in[5];
    const float* bk = (const float*)d_in[6];
    const float* wv = (const float*)d_in[7];
    const float* bv = (const float*)d_in[8];
    const float* wo = (const float*)d_in[9];
    const float* bo = (const float*)d_in[10];
    float* out = (float*)d_out;

    __nv_bfloat16 *qhi, *qlo, *khi, *klo, *vhi, *vlo, *chi, *clo;
    __nv_bfloat16 *ahi, *alo, *bhi, *blo;
    cudaGetSymbolAddress((void**)&qhi, g_qhi);
    cudaGetSymbolAddress((void**)&qlo, g_qlo);
    cudaGetSymbolAddress((void**)&khi, g_khi);
    cudaGetSymbolAddress((void**)&klo, g_klo);
    cudaGetSymbolAddress((void**)&vhi, g_vhi);
    cudaGetSymbolAddress((void**)&vlo, g_vlo);
    cudaGetSymbolAddress((void**)&chi, g_chi);
    cudaGetSymbolAddress((void**)&clo, g_clo);
    cudaGetSymbolAddress((void**)&ahi, g_ahi);
    cudaGetSymbolAddress((void**)&alo, g_alo);
    cudaGetSymbolAddress((void**)&bhi, g_bhi);
    cudaGetSymbolAddress((void**)&blo, g_blo);

    cudaFuncSetAttribute(gemm_tc_kernel,
                         cudaFuncAttributeMaxDynamicSharedMemorySize, GSMEM);
    cudaFuncSetAttribute(attn_tc_kernel,
                         cudaFuncAttributeMaxDynamicSharedMemorySize, A_SMEM);

    const int n4 = MTOT * DM / 4;
    const dim3 sgrid(n4 / 256);
    const dim3 wgrid(32, 32);
    const dim3 ggrid(DM / TN, MTOT / TM);

    // Q projection (scale 1/8 folded in)
    wsplit_kernel<<<wgrid, 256>>>(wq, bhi, blo);
    split_kernel<<<sgrid, 256>>>((const float4*)q,
        (__nv_bfloat162*)ahi, (__nv_bfloat162*)alo, n4);
    gemm_tc_kernel<<<ggrid, 256, GSMEM>>>(ahi, alo, bhi, blo, bq,
                                          nullptr, qhi, qlo, 0.125f);
    // K projection
    wsplit_kernel<<<wgrid, 256>>>(wk, bhi, blo);
    split_kernel<<<sgrid, 256>>>((const float4*)k,
        (__nv_bfloat162*)ahi, (__nv_bfloat162*)alo, n4);
    gemm_tc_kernel<<<ggrid, 256, GSMEM>>>(ahi, alo, bhi, blo, bk,
                                          nullptr, khi, klo, 1.0f);
    // V projection
    wsplit_kernel<<<wgrid, 256>>>(wv, bhi, blo);
    split_kernel<<<sgrid, 256>>>((const float4*)v,
        (__nv_bfloat162*)ahi, (__nv_bfloat162*)alo, n4);
    gemm_tc_kernel<<<ggrid, 256, GSMEM>>>(ahi, alo, bhi, blo, bv,
                                          nullptr, vhi, vlo, 1.0f);

    // attention (writes ctx hi/lo directly)
    const dim3 agrid(SEQ / 128, NH, BS);
    attn_tc_kernel<<<agrid, 256, A_SMEM>>>(qhi, qlo, khi, klo, vhi, vlo,
                                           chi, clo);

    // output projection (fp32 out)
    wsplit_kernel<<<wgrid, 256>>>(wo, bhi, blo);
    gemm_tc_kernel<<<ggrid, 256, GSMEM>>>(chi, clo, bhi, blo, bo,
                                          out, nullptr, nullptr, 1.0f);
}

// round 12
// speedup vs baseline: 9.0060x; 1.0451x over previous
#include <cuda_runtime.h>
#include <cuda_bf16.h>
#include <math.h>
#include <stdint.h>

#define BS   4
#define SEQ  2048
#define DM   1024
#define NH   16
#define DK   64
#define MTOT (BS * SEQ)   // 8192

// ---------------- scratch (device globals; no allocation allowed) ----------
__device__ __nv_bfloat16 g_qhi[MTOT * DM];
__device__ __nv_bfloat16 g_qlo[MTOT * DM];
__device__ __nv_bfloat16 g_khi[MTOT * DM];
__device__ __nv_bfloat16 g_klo[MTOT * DM];
__device__ __nv_bfloat16 g_vhi[MTOT * DM];
__device__ __nv_bfloat16 g_vlo[MTOT * DM];
__device__ __nv_bfloat16 g_chi[MTOT * DM];
__device__ __nv_bfloat16 g_clo[MTOT * DM];
__device__ __nv_bfloat16 g_ahi[3 * MTOT * DM];
__device__ __nv_bfloat16 g_alo[3 * MTOT * DM];
__device__ __nv_bfloat16 g_bhi[4 * DM * DM];
__device__ __nv_bfloat16 g_blo[4 * DM * DM];

// ---------------- helpers ---------------------------------------------------
__device__ __forceinline__ uint32_t smem_u32(const void* p) {
    uint32_t a;
    asm("{ .reg .u64 t; cvta.to.shared.u64 t, %1; cvt.u32.u64 %0, t; }"
        : "=r"(a) : "l"(p));
    return a;
}
__device__ __forceinline__ void cpa16(uint32_t dst, const void* src) {
    asm volatile("cp.async.cg.shared.global [%0], [%1], 16;"
                 :: "r"(dst), "l"(src));
}
#define CP_COMMIT() asm volatile("cp.async.commit_group;" ::: "memory")
#define CP_WAIT(n)  asm volatile("cp.async.wait_group %0;" :: "n"(n) : "memory")

__device__ __forceinline__ void ldsm_x4(uint32_t* r, uint32_t addr) {
    asm volatile("ldmatrix.sync.aligned.m8n8.x4.shared.b16 {%0,%1,%2,%3}, [%4];"
                 : "=r"(r[0]), "=r"(r[1]), "=r"(r[2]), "=r"(r[3]) : "r"(addr));
}
__device__ __forceinline__ void ldsm_x4_t(uint32_t* r, uint32_t addr) {
    asm volatile("ldmatrix.sync.aligned.m8n8.x4.trans.shared.b16 {%0,%1,%2,%3}, [%4];"
                 : "=r"(r[0]), "=r"(r[1]), "=r"(r[2]), "=r"(r[3]) : "r"(addr));
}
__device__ __forceinline__ void mma16816(float* c, const uint32_t* a,
                                         const uint32_t* b) {
    asm volatile(
        "mma.sync.aligned.m16n8k16.row.col.f32.bf16.bf16.f32 "
        "{%0,%1,%2,%3}, {%4,%5,%6,%7}, {%8,%9}, {%0,%1,%2,%3};"
        : "+f"(c[0]), "+f"(c[1]), "+f"(c[2]), "+f"(c[3])
        : "r"(a[0]), "r"(a[1]), "r"(a[2]), "r"(a[3]), "r"(b[0]), "r"(b[1]));
}
// pack {lo, hi} floats into bf16x2 (lower half = lo)
__device__ __forceinline__ uint32_t pk(float lo, float hi) {
    uint32_t d;
    asm("cvt.rn.bf16x2.f32 %0, %1, %2;" : "=r"(d) : "f"(hi), "f"(lo));
    return d;
}
__device__ __forceinline__ float lo_f(uint32_t d) { return __uint_as_float(d << 16); }
__device__ __forceinline__ float hi_f(uint32_t d) { return __uint_as_float(d & 0xffff0000u); }
#define SW128(o) ((o) ^ (((o) >> 3) & 0x70))

// ---------------------------------------------------------------------------
// split3: fp32 q/k/v (z-indexed) -> (hi, lo) bf16
// ---------------------------------------------------------------------------
__global__ __launch_bounds__(256) void split3_kernel(
    const float4* __restrict__ x0, const float4* __restrict__ x1,
    const float4* __restrict__ x2,
    __nv_bfloat16* __restrict__ hi, __nv_bfloat16* __restrict__ lo, int n4)
{
    const int z = blockIdx.y;
    const float4* x = (z == 0) ? x0 : (z == 1) ? x1 : x2;
    uint32_t* ho = (uint32_t*)(hi + (size_t)z * MTOT * DM);
    uint32_t* lw = (uint32_t*)(lo + (size_t)z * MTOT * DM);
    int i = blockIdx.x * 256 + threadIdx.x;
    if (i >= n4) return;
    float4 v = x[i];
    uint32_t h0 = pk(v.x, v.y), h1 = pk(v.z, v.w);
    uint32_t l0 = pk(v.x - lo_f(h0), v.y - hi_f(h0));
    uint32_t l1 = pk(v.z - lo_f(h1), v.w - hi_f(h1));
    ho[2 * i] = h0; ho[2 * i + 1] = h1;
    lw[2 * i] = l0; lw[2 * i + 1] = l1;
}

// wsplit4: W[K][N] fp32 (z-indexed) -> T_hi/T_lo [N][K] bf16 (transpose+split)
__global__ __launch_bounds__(256) void wsplit4_kernel(
    const float* __restrict__ w0, const float* __restrict__ w1,
    const float* __restrict__ w2, const float* __restrict__ w3,
    __nv_bfloat16* __restrict__ Thi, __nv_bfloat16* __restrict__ Tlo)
{
    __shared__ float t[32][33];
    const int z = blockIdx.z;
    const float* W = (z == 0) ? w0 : (z == 1) ? w1 : (z == 2) ? w2 : w3;
    __nv_bfloat16* th = Thi + (size_t)z * DM * DM;
    __nv_bfloat16* tl = Tlo + (size_t)z * DM * DM;
    const int bn = blockIdx.x * 32;
    const int bk = blockIdx.y * 32;
    const int x  = threadIdx.x & 31;
    const int y4 = (threadIdx.x >> 5) * 4;
#pragma unroll
    for (int j = 0; j < 4; j++)
        t[y4 + j][x] = W[(size_t)(bk + y4 + j) * DM + bn + x];
    __syncthreads();
#pragma unroll
    for (int j = 0; j < 4; j++) {
        float v = t[x][y4 + j];
        __nv_bfloat16 h = __float2bfloat16(v);
        __nv_bfloat16 l = __float2bfloat16(v - __bfloat162float(h));
        size_t o = (size_t)(bn + y4 + j) * DM + bk + x;
        th[o] = h; tl[o] = l;
    }
}

// ---------------------------------------------------------------------------
// HMMA GEMM body: C = A[M,K] @ B^T[N,K] + bias (then * scale), split-bf16.
// ---------------------------------------------------------------------------
#define TM 128
#define TN 128
#define TK 64
#define KTILES (DM / TK)
#define SUBTILE 16384
#define BUFSZ   (4 * SUBTILE)
#define GSMEM   (1024 + 2 * BUFSZ)

__device__ __forceinline__ void issue_tile(
    uint32_t bufaddr,
    const __nv_bfloat16* gAh, const __nv_bfloat16* gAl,
    const __nv_bfloat16* gBh, const __nv_bfloat16* gBl, int tid)
{
    const __nv_bfloat16* gs[4] = {gAh, gAl, gBh, gBl};
#pragma unroll
    for (int s = 0; s < 4; s++) {
        uint32_t dst = bufaddr + s * SUBTILE;
        const __nv_bfloat16* g = gs[s];
#pragma unroll
        for (int it = 0; it < 4; it++) {
            int c = tid + it * 256;
            int row = c >> 3, col = c & 7;
            uint32_t bo = (uint32_t)(row * 128 + col * 16);
            cpa16(dst + SW128(bo), g + (size_t)row * DM + col * 8);
        }
    }
}

__device__ __forceinline__ void gemm_body(
    const __nv_bfloat16* Ahi, const __nv_bfloat16* Alo,
    const __nv_bfloat16* Bhi, const __nv_bfloat16* Blo,
    const float* bias, float* Cf,
    __nv_bfloat16* Chi, __nv_bfloat16* Clo, float scale)
{
    extern __shared__ char smraw[];
    uint32_t sb0   = smem_u32(smraw);
    uint32_t sbase = (sb0 + 1023u) & ~1023u;

    const int tid  = threadIdx.x;
    const int wid  = tid >> 5;
    const int lane = tid & 31;
    const int bm = blockIdx.y * TM;
    const int bn = blockIdx.x * TN;
    const int wm = (wid & 3) * 32;
    const int wn = (wid >> 2) * 64;

    const __nv_bfloat16* gAh = Ahi + (size_t)bm * DM;
    const __nv_bfloat16* gAl = Alo + (size_t)bm * DM;
    const __nv_bfloat16* gBh = Bhi + (size_t)bn * DM;
    const __nv_bfloat16* gBl = Blo + (size_t)bn * DM;

    const int sub = lane >> 3, rin = lane & 7;
    const int arow0 = wm + (sub & 1) * 8 + rin;
    const uint32_t aoff0 = (uint32_t)(arow0 * 128);
    const uint32_t aoff1 = (uint32_t)((arow0 + 16) * 128);
    const uint32_t amask = (uint32_t)(arow0 & 7) << 4;
    const uint32_t akadd = (uint32_t)(sub >> 1) * 16;
    const int brow0 = wn + (sub >> 1) * 8 + rin;
    const uint32_t bmask = (uint32_t)(brow0 & 7) << 4;
    const uint32_t bkadd = (uint32_t)(sub & 1) * 16;

    float acc[2][8][4];
#pragma unroll
    for (int i = 0; i < 2; i++)
#pragma unroll
        for (int j = 0; j < 8; j++)
#pragma unroll
            for (int c = 0; c < 4; c++) acc[i][j][c] = 0.f;

    issue_tile(sbase, gAh, gAl, gBh, gBl, tid);
    CP_COMMIT();

    for (int t = 0; t < KTILES; t++) {
        const uint32_t buf = sbase + (uint32_t)(t & 1) * BUFSZ;
        if (t + 1 < KTILES) {
            const int ko = (t + 1) * TK;
            issue_tile(sbase + (uint32_t)((t + 1) & 1) * BUFSZ,
                       gAh + ko, gAl + ko, gBh + ko, gBl + ko, tid);
            CP_COMMIT();
            CP_WAIT(1);
        } else {
            CP_WAIT(0);
        }
        __syncthreads();

        const uint32_t aHi = buf;
        const uint32_t aLo = buf + SUBTILE;
        const uint32_t bHi = buf + 2 * SUBTILE;
        const uint32_t bLo = buf + 3 * SUBTILE;

#pragma unroll
        for (int ks = 0; ks < 4; ks++) {
            const uint32_t kb = (uint32_t)ks * 32;
            const uint32_t aIn = (kb + akadd) ^ amask;
            const uint32_t bIn = (kb + bkadd) ^ bmask;
            uint32_t ah[2][4], al[2][4];
            ldsm_x4(ah[0], aHi + aoff0 + aIn);
            ldsm_x4(ah[1], aHi + aoff1 + aIn);
            ldsm_x4(al[0], aLo + aoff0 + aIn);
            ldsm_x4(al[1], aLo + aoff1 + aIn);
#pragma unroll
            for (int jp = 0; jp < 4; jp++) {
                const uint32_t boff = (uint32_t)((brow0 + jp * 16) * 128);
                uint32_t bh[4], bl[4];
                ldsm_x4(bh, bHi + boff + bIn);
                ldsm_x4(bl, bLo + boff + bIn);
#pragma unroll
                for (int i = 0; i < 2; i++) {
#pragma unroll
                    for (int jj = 0; jj < 2; jj++) {
                        float* c = acc[i][jp * 2 + jj];
                        mma16816(c, ah[i], bh + jj * 2);
                        mma16816(c, ah[i], bl + jj * 2);
                        mma16816(c, al[i], bh + jj * 2);
                    }
                }
            }
        }
        __syncthreads();
    }

    const int g4 = lane >> 2, l4 = lane & 3;
#pragma unroll
    for (int i = 0; i < 2; i++) {
        const int row = bm + wm + i * 16 + g4;
#pragma unroll
        for (int j = 0; j < 8; j++) {
            const int col = bn + wn + j * 8 + l4 * 2;
            const float b0 = bias[col], b1 = bias[col + 1];
            float o0 = (acc[i][j][0] + b0) * scale;
            float o1 = (acc[i][j][1] + b1) * scale;
            float o2 = (acc[i][j][2] + b0) * scale;
            float o3 = (acc[i][j][3] + b1) * scale;
            if (Cf) {
                *(float2*)&Cf[(size_t)row * DM + col]       = make_float2(o0, o1);
                *(float2*)&Cf[(size_t)(row + 8) * DM + col] = make_float2(o2, o3);
            } else {
                uint32_t h0 = pk(o0, o1);
                uint32_t l0 = pk(o0 - lo_f(h0), o1 - hi_f(h0));
                uint32_t h1 = pk(o2, o3);
                uint32_t l1 = pk(o2 - lo_f(h1), o3 - hi_f(h1));
                *(uint32_t*)&Chi[(size_t)row * DM + col]       = h0;
                *(uint32_t*)&Clo[(size_t)row * DM + col]       = l0;
                *(uint32_t*)&Chi[(size_t)(row + 8) * DM + col] = h1;
                *(uint32_t*)&Clo[(size_t)(row + 8) * DM + col] = l1;
            }
        }
    }
}

// QKV: one launch, z = 0/1/2
__global__ __launch_bounds__(256) void gemm_qkv_kernel(
    const __nv_bfloat16* __restrict__ Ahi, const __nv_bfloat16* __restrict__ Alo,
    const __nv_bfloat16* __restrict__ Bhi, const __nv_bfloat16* __restrict__ Blo,
    const float* __restrict__ bq, const float* __restrict__ bk,
    const float* __restrict__ bv,
    __nv_bfloat16* __restrict__ qh, __nv_bfloat16* __restrict__ ql,
    __nv_bfloat16* __restrict__ kh, __nv_bfloat16* __restrict__ kl,
    __nv_bfloat16* __restrict__ vh, __nv_bfloat16* __restrict__ vl)
{
    const int z = blockIdx.z;
    const size_t ao = (size_t)z * MTOT * DM;
    const size_t wo = (size_t)z * DM * DM;
    const float* bias = (z == 0) ? bq : (z == 1) ? bk : bv;
    __nv_bfloat16* Ch = (z == 0) ? qh : (z == 1) ? kh : vh;
    __nv_bfloat16* Cl = (z == 0) ? ql : (z == 1) ? kl : vl;
    const float scale = (z == 0) ? 0.125f : 1.0f;
    gemm_body(Ahi + ao, Alo + ao, Bhi + wo, Blo + wo, bias,
              nullptr, Ch, Cl, scale);
}

// O projection: fp32 output, weight block z=3
__global__ __launch_bounds__(256) void gemm_o_kernel(
    const __nv_bfloat16* __restrict__ Ahi, const __nv_bfloat16* __restrict__ Alo,
    const __nv_bfloat16* __restrict__ Bhi, const __nv_bfloat16* __restrict__ Blo,
    const float* __restrict__ bias, float* __restrict__ Cf)
{
    const size_t wo = (size_t)3 * DM * DM;
    gemm_body(Ahi, Alo, Bhi + wo, Blo + wo, bias, Cf, nullptr, nullptr, 1.0f);
}

// ---------------------------------------------------------------------------
// Flash attention on HMMA, split-bf16 Q/K/V/P.
// CTA = (b, h, 64 q-rows); 4 warps x 16 q-rows; KV tiles of 64, double buffer.
// 81KB smem -> 2 CTAs / SM.
// ---------------------------------------------------------------------------
#define ACT    64
#define NKVT   (SEQ / ACT)      // 32
#define AQT    64
#define AQH    0
#define AQL    8192
#define ASKV   16384            // per-buffer: KH,KL,VH,VL each 8192
#define AKVBUF 32768
#define A_SMEM (1024 + ASKV + 2 * AKVBUF)   // 1KB slack + 80KB

__device__ __forceinline__ void issue_kv(
    uint32_t dst,
    const __nv_bfloat16* Kh, const __nv_bfloat16* Kl,
    const __nv_bfloat16* Vh, const __nv_bfloat16* Vl,
    size_t grow, int hoff, int tid)
{
    const __nv_bfloat16* gs[4] = {Kh, Kl, Vh, Vl};
#pragma unroll
    for (int s = 0; s < 4; s++) {
        const __nv_bfloat16* g = gs[s] + grow * DM + hoff;
#pragma unroll
        for (int it = 0; it < 4; it++) {
            int c = tid + it * 128;          // 0..511
            int r = c >> 3, cc = c & 7;
            uint32_t bo = SW128((uint32_t)(r * 128 + cc * 16));
            cpa16(dst + s * 8192 + bo, g + (size_t)r * DM + cc * 8);
        }
    }
}

__global__ __launch_bounds__(128, 2) void attn_tc_kernel(
    const __nv_bfloat16* __restrict__ Qh, const __nv_bfloat16* __restrict__ Ql,
    const __nv_bfloat16* __restrict__ Kh, const __nv_bfloat16* __restrict__ Kl,
    const __nv_bfloat16* __restrict__ Vh, const __nv_bfloat16* __restrict__ Vl,
    __nv_bfloat16* __restrict__ Ch, __nv_bfloat16* __restrict__ Cl)
{
    extern __shared__ char smraw[];
    uint32_t sb0   = smem_u32(smraw);
    uint32_t sbase = (sb0 + 1023u) & ~1023u;

    const int tid = threadIdx.x, wid = tid >> 5, lane = tid & 31;
    const int b = blockIdx.z, h = blockIdx.y, qt = blockIdx.x;
    const size_t row0   = (size_t)(b * SEQ + qt * AQT);
    const size_t kvrow0 = (size_t)b * SEQ;
    const int hoff = h * DK;

    // ---- load Q hi/lo (8KB each) ----
#pragma unroll
    for (int it = 0; it < 4; it++) {
        int c = tid + it * 128;              // 0..511
        int r = c >> 3, cc = c & 7;
        uint32_t bo = SW128((uint32_t)(r * 128 + cc * 16));
        cpa16(sbase + AQH + bo, Qh + (row0 + r) * DM + hoff + cc * 8);
        cpa16(sbase + AQL + bo, Ql + (row0 + r) * DM + hoff + cc * 8);
    }
    issue_kv(sbase + ASKV, Kh, Kl, Vh, Vl, kvrow0, hoff, tid);
    CP_COMMIT();

    // ---- per-lane fragment address components ----
    const int sub = lane >> 3, rin = lane & 7;
    const uint32_t xm = (uint32_t)rin << 4;
    const uint32_t a_row = (uint32_t)((wid * 16 + (sub & 1) * 8 + rin) * 128);
    const uint32_t a_byte = (uint32_t)(sub >> 1) * 16;
    const uint32_t k_row = (uint32_t)(((sub >> 1) * 8 + rin) * 128);
    const uint32_t k_byte = (uint32_t)(sub & 1) * 16;
    const uint32_t v_row = (uint32_t)(((sub & 1) * 8 + rin) * 128);
    const uint32_t v_byte = (uint32_t)(sub >> 1) * 16;

    float oA[8][4];
#pragma unroll
    for (int j = 0; j < 8; j++)
#pragma unroll
        for (int c = 0; c < 4; c++) oA[j][c] = 0.f;
    float m0 = -INFINITY, m1 = -INFINITY, lsum0 = 0.f, lsum1 = 0.f;

    for (int t = 0; t < NKVT; t++) {
        const uint32_t buf = sbase + ASKV + (uint32_t)(t & 1) * AKVBUF;
        if (t + 1 < NKVT) {
            issue_kv(sbase + ASKV + (uint32_t)((t + 1) & 1) * AKVBUF,
                     Kh, Kl, Vh, Vl, kvrow0 + (size_t)(t + 1) * ACT, hoff, tid);
            CP_COMMIT();
            CP_WAIT(1);
        } else {
            CP_WAIT(0);
        }
        __syncthreads();

        const uint32_t bKH = buf, bKL = buf + 8192;
        const uint32_t bVH = buf + 16384, bVL = buf + 24576;

        // ---- S = Q K^T (3 products) ----
        float sA[8][4];
#pragma unroll
        for (int j = 0; j < 8; j++)
#pragma unroll
            for (int c = 0; c < 4; c++) sA[j][c] = 0.f;

#pragma unroll
        for (int ks = 0; ks < 4; ks++) {
            const uint32_t aIn = ((uint32_t)ks * 32 + a_byte) ^ xm;
            const uint32_t kIn = ((uint32_t)ks * 32 + k_byte) ^ xm;
            uint32_t qh[4], ql[4], kf[16];
            ldsm_x4(qh, sbase + AQH + a_row + aIn);
            ldsm_x4(ql, sbase + AQL + a_row + aIn);
#pragma unroll
            for (int jb = 0; jb < 8; jb += 2)
                ldsm_x4(kf + jb * 2, bKH + (uint32_t)jb * 1024 + k_row + kIn);
#pragma unroll
            for (int j = 0; j < 8; j++) {
                mma16816(sA[j], qh, kf + 2 * j);
                mma16816(sA[j], ql, kf + 2 * j);
            }
#pragma unroll
            for (int jb = 0; jb < 8; jb += 2)
                ldsm_x4(kf + jb * 2, bKL + (uint32_t)jb * 1024 + k_row + kIn);
#pragma unroll
            for (int j = 0; j < 8; j++)
                mma16816(sA[j], qh, kf + 2 * j);
        }

        // ---- online softmax ----
        float mt0 = -INFINITY, mt1 = -INFINITY;
#pragma unroll
        for (int j = 0; j < 8; j++) {
            mt0 = fmaxf(mt0, fmaxf(sA[j][0], sA[j][1]));
            mt1 = fmaxf(mt1, fmaxf(sA[j][2], sA[j][3]));
        }
        mt0 = fmaxf(mt0, __shfl_xor_sync(0xffffffffu, mt0, 1));
        mt0 = fmaxf(mt0, __shfl_xor_sync(0xffffffffu, mt0, 2));
        mt1 = fmaxf(mt1, __shfl_xor_sync(0xffffffffu, mt1, 1));
        mt1 = fmaxf(mt1, __shfl_xor_sync(0xffffffffu, mt1, 2));
        const float mn0 = fmaxf(m0, mt0), mn1 = fmaxf(m1, mt1);
        const float cr0 = __expf(m0 - mn0), cr1 = __expf(m1 - mn1);
        float ps0 = 0.f, ps1 = 0.f;
#pragma unroll
        for (int j = 0; j < 8; j++) {
            sA[j][0] = __expf(sA[j][0] - mn0); ps0 += sA[j][0];
            sA[j][1] = __expf(sA[j][1] - mn0); ps0 += sA[j][1];
            sA[j][2] = __expf(sA[j][2] - mn1); ps1 += sA[j][2];
            sA[j][3] = __expf(sA[j][3] - mn1); ps1 += sA[j][3];
        }
        ps0 += __shfl_xor_sync(0xffffffffu, ps0, 1);
        ps0 += __shfl_xor_sync(0xffffffffu, ps0, 2);
        ps1 += __shfl_xor_sync(0xffffffffu, ps1, 1);
        ps1 += __shfl_xor_sync(0xffffffffu, ps1, 2);
        lsum0 = lsum0 * cr0 + ps0;
        lsum1 = lsum1 * cr1 + ps1;
        m0 = mn0; m1 = mn1;
#pragma unroll
        for (int j = 0; j < 8; j++) {
            oA[j][0] *= cr0; oA[j][1] *= cr0;
            oA[j][2] *= cr1; oA[j][3] *= cr1;
        }

        // ---- O += P V (3 products); P frags in registers ----
#pragma unroll
        for (int kb = 0; kb < 4; kb++) {
            const float* p0 = sA[2 * kb];
            const float* p1 = sA[2 * kb + 1];
            uint32_t pha[4], pla[4];
            pha[0] = pk(p0[0], p0[1]);
            pha[1] = pk(p0[2], p0[3]);
            pha[2] = pk(p1[0], p1[1]);
            pha[3] = pk(p1[2], p1[3]);
            pla[0] = pk(p0[0] - lo_f(pha[0]), p0[1] - hi_f(pha[0]));
            pla[1] = pk(p0[2] - lo_f(pha[1]), p0[3] - hi_f(pha[1]));
            pla[2] = pk(p1[0] - lo_f(pha[2]), p1[1] - hi_f(pha[2]));
            pla[3] = pk(p1[2] - lo_f(pha[3]), p1[3] - hi_f(pha[3]));
            const uint32_t vrow = (uint32_t)kb * 2048 + v_row;
#pragma unroll
            for (int jb = 0; jb < 8; jb += 2) {
                const uint32_t vIn = ((uint32_t)jb * 16 + v_byte) ^ xm;
                uint32_t vf[4];
                ldsm_x4_t(vf, bVH + vrow + vIn);
                mma16816(oA[jb],     pha, vf + 0);
                mma16816(oA[jb + 1], pha, vf + 2);
                mma16816(oA[jb],     pla, vf + 0);
                mma16816(oA[jb + 1], pla, vf + 2);
                ldsm_x4_t(vf, bVL + vrow + vIn);
                mma16816(oA[jb],     pha, vf + 0);
                mma16816(oA[jb + 1], pha, vf + 2);
            }
        }
        __syncthreads();
    }

    // ---- epilogue ----
    const float inv0 = 1.f / lsum0, inv1 = 1.f / lsum1;
    const size_t orow = row0 + wid * 16 + (lane >> 2);
    const int col = hoff + (lane & 3) * 2;
#pragma unroll
    for (int j = 0; j < 8; j++) {
        float o0 = oA[j][0] * inv0, o1 = oA[j][1] * inv0;
        float o2 = oA[j][2] * inv1, o3 = oA[j][3] * inv1;
        uint32_t h0 = pk(o0, o1);
        uint32_t l0 = pk(o0 - lo_f(h0), o1 - hi_f(h0));
        uint32_t h1 = pk(o2, o3);
        uint32_t l1 = pk(o2 - lo_f(h1), o3 - hi_f(h1));
        *(uint32_t*)&Ch[orow * DM + col + j * 8]       = h0;
        *(uint32_t*)&Cl[orow * DM + col + j * 8]       = l0;
        *(uint32_t*)&Ch[(orow + 8) * DM + col + j * 8] = h1;
        *(uint32_t*)&Cl[(orow + 8) * DM + col + j * 8] = l1;
    }
}

// ---------------------------------------------------------------------------
extern "C" void kernel_launch(void* const* d_in, const int* in_sizes, int n_in,
                              void* d_out, int out_size)
{
    const float* q  = (const float*)d_in[0];
    const float* k  = (const float*)d_in[1];
    const float* v  = (const float*)d_in[2];
    const float* wq = (const float*)d_in[3];
    const float* bq = (const float*)d_in[4];
    const float* wk = (const float*)d_in[5];
    const float* bk = (const float*)d_in[6];
    const float* wv = (const float*)d_in[7];
    const float* bv = (const float*)d_in[8];
    const float* wo = (const float*)d_in[9];
    const float* bo = (const float*)d_in[10];
    float* out = (float*)d_out;

    __nv_bfloat16 *qhi, *qlo, *khi, *klo, *vhi, *vlo, *chi, *clo;
    __nv_bfloat16 *ahi, *alo, *bhi, *blo;
    cudaGetSymbolAddress((void**)&qhi, g_qhi);
    cudaGetSymbolAddress((void**)&qlo, g_qlo);
    cudaGetSymbolAddress((void**)&khi, g_khi);
    cudaGetSymbolAddress((void**)&klo, g_klo);
    cudaGetSymbolAddress((void**)&vhi, g_vhi);
    cudaGetSymbolAddress((void**)&vlo, g_vlo);
    cudaGetSymbolAddress((void**)&chi, g_chi);
    cudaGetSymbolAddress((void**)&clo, g_clo);
    cudaGetSymbolAddress((void**)&ahi, g_ahi);
    cudaGetSymbolAddress((void**)&alo, g_alo);
    cudaGetSymbolAddress((void**)&bhi, g_bhi);
    cudaGetSymbolAddress((void**)&blo, g_blo);

    cudaFuncSetAttribute(gemm_qkv_kernel,
                         cudaFuncAttributeMaxDynamicSharedMemorySize, GSMEM);
    cudaFuncSetAttribute(gemm_o_kernel,
                         cudaFuncAttributeMaxDynamicSharedMemorySize, GSMEM);
    cudaFuncSetAttribute(attn_tc_kernel,
                         cudaFuncAttributeMaxDynamicSharedMemorySize, A_SMEM);

    const int n4 = MTOT * DM / 4;

    // all weight transposes+splits in one launch
    wsplit4_kernel<<<dim3(32, 32, 4), 256>>>(wq, wk, wv, wo, bhi, blo);
    // all activation splits in one launch
    split3_kernel<<<dim3(n4 / 256, 3), 256>>>(
        (const float4*)q, (const float4*)k, (const float4*)v, ahi, alo, n4);
    // Q,K,V projections in one launch (z = 0,1,2)
    gemm_qkv_kernel<<<dim3(DM / TN, MTOT / TM, 3), 256, GSMEM>>>(
        ahi, alo, bhi, blo, bq, bk, bv,
        qhi, qlo, khi, klo, vhi, vlo);
    // attention
    attn_tc_kernel<<<dim3(SEQ / AQT, NH, BS), 128, A_SMEM>>>(
        qhi, qlo, khi, klo, vhi, vlo, chi, clo);
    // output projection
    gemm_o_kernel<<<dim3(DM / TN, MTOT / TM), 256, GSMEM>>>(
        chi, clo, bhi, blo, bo, out);
}